// round 7
// baseline (speedup 1.0000x reference)
#include <cuda_runtime.h>
#include <cuda_fp16.h>
#include <cstdint>
#include <math.h>

// Problem constants
#define B_      8
#define SEQ_    1024
#define DV_     1152
#define DT_     2048
#define V_      32000
#define MROWS   2048
#define DSHUF   4608
#define LN_EPS  1e-5f

// GEMM tiling (fp16 operands): 8 warps, 128x256 CTA tile, 64x64 warp tile
#define BM      128
#define BN      256
#define BKH     64                 // K elems per stage
#define STAGES  3
#define NTH     256
#define ASTG    (BM * 128)         // 16KB: 128 rows x 128B
#define BSTG    (BN * 128)         // 32KB: NT 256 n-rows x 128B; NN 64 k-rows x 512B
#define STGB    (ASTG + BSTG)      // 49152
#define SMEM_DYN (STAGES * STGB)   // 147456

// Scratch (device globals: allocation-guard-safe)
__device__ __half g_Xh [(size_t)MROWS * DSHUF];
__device__ __half g_W1h[(size_t)DT_   * DSHUF];
__device__ float  g_F  [(size_t)MROWS * DT_];
__device__ __half g_Fh [(size_t)MROWS * DT_];
__device__ __half g_W2h[(size_t)V_    * DT_];
__device__ __half g_Eh [(size_t)V_    * DT_];    // embed as half, original [V, DT]
__device__ __half g_Ph [(size_t)MROWS * V_];     // exp(logits), half
__device__ float  g_Zinv[MROWS];

// ---------------------------------------------------------------------------
// helpers
// ---------------------------------------------------------------------------
__device__ __forceinline__ uint32_t smem_u32(const void* p) {
    uint32_t a;
    asm("{ .reg .u64 t; cvta.to.shared.u64 t, %1; cvt.u32.u64 %0, t; }" : "=r"(a) : "l"(p));
    return a;
}
#define CP16(d, s) \
    asm volatile("cp.async.cg.shared.global [%0], [%1], 16;" :: "r"(d), "l"(s))
#define CP_COMMIT()  asm volatile("cp.async.commit_group;")
#define CP_WAIT(n)   asm volatile("cp.async.wait_group %0;" :: "n"(n))

__device__ __forceinline__ void ldsm4(uint32_t& r0, uint32_t& r1, uint32_t& r2,
                                      uint32_t& r3, uint32_t a) {
    asm volatile("ldmatrix.sync.aligned.m8n8.x4.shared.b16 {%0,%1,%2,%3}, [%4];"
                 : "=r"(r0), "=r"(r1), "=r"(r2), "=r"(r3) : "r"(a));
}
__device__ __forceinline__ void ldsm4t(uint32_t& r0, uint32_t& r1, uint32_t& r2,
                                       uint32_t& r3, uint32_t a) {
    asm volatile("ldmatrix.sync.aligned.m8n8.x4.trans.shared.b16 {%0,%1,%2,%3}, [%4];"
                 : "=r"(r0), "=r"(r1), "=r"(r2), "=r"(r3) : "r"(a));
}
__device__ __forceinline__ void mma_f16(float* d, const uint32_t* a,
                                        uint32_t b0, uint32_t b1) {
    asm volatile(
        "mma.sync.aligned.m16n8k16.row.col.f32.f16.f16.f32 "
        "{%0,%1,%2,%3}, {%4,%5,%6,%7}, {%8,%9}, {%0,%1,%2,%3};"
        : "+f"(d[0]), "+f"(d[1]), "+f"(d[2]), "+f"(d[3])
        : "r"(a[0]), "r"(a[1]), "r"(a[2]), "r"(a[3]), "r"(b0), "r"(b1));
}

// ---------------------------------------------------------------------------
// fp16 GEMM, f32 accumulate. 256 threads, 128x256 tile, 64x64 warp tiles,
// BK=64, 3-stage cp.async pipeline.
//   NN=false: C = A[M,K] * B[N,K]^T   (B K-major)
//   NN=true : C = A[M,K] * B[K,N]     (B N-major, ldmatrix.trans fragments)
// MODE: 0 = f32 store; 1 = half(exp(acc)); 2 = f32 * scale[row].
// ---------------------------------------------------------------------------
template<int MODE, bool NN>
__global__ __launch_bounds__(NTH, 1)
void gemm_h(const __half* __restrict__ A, const __half* __restrict__ Bw,
            void* __restrict__ Cv, const float* __restrict__ scale,
            int M, int N, int K)
{
    extern __shared__ __align__(128) char sm[];
    const uint32_t sb = smem_u32(sm);
    const int tid  = threadIdx.x;
    const int warp = tid >> 5;
    const int lane = tid & 31;
    const int gq   = lane >> 2;
    const int tg   = lane & 3;
    const int wm   = (warp & 1) * 64;     // 2 warps in m
    const int wn   = (warp >> 1) * 64;    // 4 warps in n
    const int bm   = blockIdx.x * BM;
    const int bn   = blockIdx.y * BN;
    const int NK   = K / BKH;
    const int rl   = lane & 15;    // ldmatrix row-in-tile
    const int kh   = lane >> 4;    // ldmatrix half-select

    auto load_stage = [&](int f, int slot) {
        const uint32_t sA = sb + (uint32_t)slot * STGB;
        const uint32_t sB = sA + ASTG;
        const __half* Ag = A + (size_t)bm * K + (size_t)f * BKH;
#pragma unroll
        for (int t = 0; t < 4; t++) {            // A: 128 rows x 8 chunks
            int c = tid + t * NTH;
            int row = c >> 3, g = c & 7;
            CP16(sA + row * 128 + ((g ^ (row & 7)) << 4),
                 Ag + (size_t)row * K + g * 8);
        }
        if (!NN) {
            const __half* Bg = Bw + (size_t)bn * K + (size_t)f * BKH;
#pragma unroll
            for (int t = 0; t < 8; t++) {        // B: 256 n-rows x 8 chunks
                int c = tid + t * NTH;
                int row = c >> 3, g = c & 7;
                CP16(sB + row * 128 + ((g ^ (row & 7)) << 4),
                     Bg + (size_t)row * K + g * 8);
            }
        } else {
            const __half* Bg = Bw + (size_t)f * BKH * N + bn;
#pragma unroll
            for (int t = 0; t < 8; t++) {        // B: 64 k-rows x 32 chunks (512B/row)
                int c = tid + t * NTH;
                int krow = c >> 5, ng = c & 31;
                CP16(sB + krow * 512 + ((ng ^ (krow & 7)) << 4),
                     Bg + (size_t)krow * N + ng * 8);
            }
        }
    };

    float acc[4][8][4];
#pragma unroll
    for (int i = 0; i < 4; i++)
#pragma unroll
        for (int j = 0; j < 8; j++)
#pragma unroll
            for (int r = 0; r < 4; r++) acc[i][j][r] = 0.f;

    load_stage(0, 0); CP_COMMIT();
    load_stage(1, 1); CP_COMMIT();

    int slot = 0;
    for (int i = 0; i < NK; i++) {
        CP_WAIT(1);
        __syncthreads();

        const uint32_t sA = sb + (uint32_t)slot * STGB;
        const uint32_t sB = sA + ASTG;

#pragma unroll
        for (int ks = 0; ks < 4; ks++) {
            uint32_t a[4][4];
            {
                const int g = ks * 2 + kh;
#pragma unroll
                for (int mi = 0; mi < 4; mi++) {
                    int row = wm + mi * 16 + rl;
                    ldsm4(a[mi][0], a[mi][1], a[mi][2], a[mi][3],
                          sA + row * 128 + ((g ^ (row & 7)) << 4));
                }
            }
            uint32_t bf[4][4];
            if (!NN) {
                const int g = ks * 2 + kh;
#pragma unroll
                for (int n2 = 0; n2 < 4; n2++) {
                    int row = wn + n2 * 16 + rl;
                    ldsm4(bf[n2][0], bf[n2][1], bf[n2][2], bf[n2][3],
                          sB + row * 128 + ((g ^ (row & 7)) << 4));
                }
#pragma unroll
                for (int mi = 0; mi < 4; mi++)
#pragma unroll
                    for (int ni = 0; ni < 8; ni++)
                        mma_f16(acc[mi][ni], a[mi],
                                bf[ni >> 1][ni & 1], bf[ni >> 1][(ni & 1) + 2]);
            } else {
                // trans load: each ldsm4t covers 16 k-rows x 16 n-cols.
#pragma unroll
                for (int n2 = 0; n2 < 4; n2++) {
                    int krow = ks * 16 + rl;
                    int ng = ((wn + n2 * 16) >> 3) + kh;
                    ldsm4t(bf[n2][0], bf[n2][1], bf[n2][2], bf[n2][3],
                           sB + krow * 512 + ((ng ^ (krow & 7)) << 4));
                }
                // trans reg order: {n-lo/k-lo, n-lo/k-hi, n-hi/k-lo, n-hi/k-hi}
#pragma unroll
                for (int mi = 0; mi < 4; mi++)
#pragma unroll
                    for (int ni = 0; ni < 8; ni++)
                        mma_f16(acc[mi][ni], a[mi],
                                bf[ni >> 1][(ni & 1) * 2], bf[ni >> 1][(ni & 1) * 2 + 1]);
            }
        }
        __syncthreads();

        const int f = i + STAGES - 1;
        if (f < NK) {
            int ws = slot + STAGES - 1; if (ws >= STAGES) ws -= STAGES;
            load_stage(f, ws);
        }
        CP_COMMIT();                 // unconditional: stable group FIFO
        if (++slot == STAGES) slot = 0;
    }

    // ---- epilogue ----
#pragma unroll
    for (int mi = 0; mi < 4; mi++) {
        const int r0 = bm + wm + mi * 16 + gq;
#pragma unroll
        for (int ni = 0; ni < 8; ni++) {
            const int c0 = bn + wn + ni * 8 + tg * 2;
            const float* ap = acc[mi][ni];
            if (MODE == 0) {
                float* C = (float*)Cv;
                *(float2*)(C + (size_t)r0 * N + c0)       = make_float2(ap[0], ap[1]);
                *(float2*)(C + (size_t)(r0 + 8) * N + c0) = make_float2(ap[2], ap[3]);
            } else if (MODE == 1) {
                __half2* C = (__half2*)Cv;
                C[((size_t)r0 * N + c0) >> 1] =
                    __floats2half2_rn(__expf(ap[0]), __expf(ap[1]));
                C[((size_t)(r0 + 8) * N + c0) >> 1] =
                    __floats2half2_rn(__expf(ap[2]), __expf(ap[3]));
            } else {
                const float s0 = scale[r0], s1 = scale[r0 + 8];
                float* C = (float*)Cv;
                *(float2*)(C + (size_t)r0 * N + c0)       = make_float2(ap[0] * s0, ap[1] * s0);
                *(float2*)(C + (size_t)(r0 + 8) * N + c0) = make_float2(ap[2] * s1, ap[3] * s1);
            }
        }
    }
}

// ---------------------------------------------------------------------------
// pixel shuffle gather -> half (float2 -> half2)
// ---------------------------------------------------------------------------
__global__ void shuffle_kernel(const float* __restrict__ vf, __half2* __restrict__ X) {
    long i2 = (long)blockIdx.x * blockDim.x + threadIdx.x;
    const long total2 = (long)MROWS * DSHUF / 2;
    if (i2 >= total2) return;
    int e  = (int)(i2 % (DSHUF / 2)) * 2;
    long rl = i2 / (DSHUF / 2);
    int l  = (int)(rl % 256);
    int b  = (int)(rl / 256);
    int d  = e % DV_;
    int h  = 2 * (l >> 4) + (e / (2 * DV_));
    int w  = 2 * (l & 15) + ((e % (2 * DV_)) / DV_);
    float2 v = *(const float2*)(vf + ((long)b * SEQ_ + h * 32 + w) * DV_ + d);
    X[i2] = __floats2half2_rn(v.x, v.y);
}

// ---------------------------------------------------------------------------
// f32 -> half convert copy
// ---------------------------------------------------------------------------
__global__ void cvt_half(const float4* __restrict__ in, __half2* __restrict__ out, long n4) {
    long i = (long)blockIdx.x * blockDim.x + threadIdx.x;
    if (i >= n4) return;
    float4 v = in[i];
    out[2 * i]     = __floats2half2_rn(v.x, v.y);
    out[2 * i + 1] = __floats2half2_rn(v.z, v.w);
}

// ---------------------------------------------------------------------------
// block reduce
// ---------------------------------------------------------------------------
__device__ __forceinline__ float block_reduce_sum(float v) {
    __shared__ float sh[32];
    int lane = threadIdx.x & 31, wid = threadIdx.x >> 5;
#pragma unroll
    for (int o = 16; o > 0; o >>= 1) v += __shfl_xor_sync(0xffffffff, v, o);
    if (lane == 0) sh[wid] = v;
    __syncthreads();
    int nw = blockDim.x >> 5;
    v = (threadIdx.x < nw) ? sh[threadIdx.x] : 0.f;
    if (wid == 0) {
#pragma unroll
        for (int o = 16; o > 0; o >>= 1) v += __shfl_xor_sync(0xffffffff, v, o);
        if (lane == 0) sh[0] = v;
    }
    __syncthreads();
    float r = sh[0];
    __syncthreads();
    return r;
}

// ---------------------------------------------------------------------------
// bias + LayerNorm: F(f32) -> Fh(half)
// ---------------------------------------------------------------------------
__global__ void ln_kernel(const float* __restrict__ F, const float* __restrict__ bias,
                          __half* __restrict__ Fh) {
    const float* p = F + (size_t)blockIdx.x * DT_;
    __half* o = Fh + (size_t)blockIdx.x * DT_;
    float s = 0.f, ss = 0.f;
    for (int i = threadIdx.x; i < DT_; i += blockDim.x) {
        float v = p[i] + bias[i];
        s += v; ss += v * v;
    }
    s  = block_reduce_sum(s);
    ss = block_reduce_sum(ss);
    float mu  = s * (1.0f / DT_);
    float var = ss * (1.0f / DT_) - mu * mu;
    float rstd = rsqrtf(var + LN_EPS);
    for (int i = threadIdx.x; i < DT_; i += blockDim.x)
        o[i] = __float2half_rn((p[i] + bias[i] - mu) * rstd);
}

// ---------------------------------------------------------------------------
// Zinv[r] = 1 / sum(Ph[r,:])
// ---------------------------------------------------------------------------
__global__ void rowsum_kernel(const __half2* __restrict__ Ph, float* __restrict__ Zinv) {
    const __half2* p = Ph + (size_t)blockIdx.x * (V_ / 2);
    float s = 0.f;
    for (int i = threadIdx.x; i < V_ / 2; i += blockDim.x) {
        float2 f = __half22float2(p[i]);
        s += f.x + f.y;
    }
    s = block_reduce_sum(s);
    if (threadIdx.x == 0) Zinv[blockIdx.x] = 1.0f / s;
}

// ---------------------------------------------------------------------------
// Launch
// ---------------------------------------------------------------------------
extern "C" void kernel_launch(void* const* d_in, const int* in_sizes, int n_in,
                              void* d_out, int out_size) {
    const float* vf    = (const float*)d_in[0];  // vision_feats
    const float* embed = (const float*)d_in[1];  // llm_token_embed (32000,2048)
    const float* W1w   = (const float*)d_in[2];  // (2048,4608)
    const float* W1b   = (const float*)d_in[3];  // (2048,)
    const float* W2w   = (const float*)d_in[4];  // (32000,2048)
    float* out = (float*)d_out;                  // (8,256,2048) f32

    __half *Xh, *W1h, *Fh, *W2h, *Eh, *Ph;
    float *F, *Zinv;
    cudaGetSymbolAddress((void**)&Xh,   g_Xh);
    cudaGetSymbolAddress((void**)&W1h,  g_W1h);
    cudaGetSymbolAddress((void**)&F,    g_F);
    cudaGetSymbolAddress((void**)&Fh,   g_Fh);
    cudaGetSymbolAddress((void**)&W2h,  g_W2h);
    cudaGetSymbolAddress((void**)&Eh,   g_Eh);
    cudaGetSymbolAddress((void**)&Ph,   g_Ph);
    cudaGetSymbolAddress((void**)&Zinv, g_Zinv);

    cudaFuncSetAttribute(gemm_h<0,false>, cudaFuncAttributeMaxDynamicSharedMemorySize, SMEM_DYN);
    cudaFuncSetAttribute(gemm_h<1,false>, cudaFuncAttributeMaxDynamicSharedMemorySize, SMEM_DYN);
    cudaFuncSetAttribute(gemm_h<2,true>,  cudaFuncAttributeMaxDynamicSharedMemorySize, SMEM_DYN);

    // 1) pixel shuffle -> half
    {
        long total2 = (long)MROWS * DSHUF / 2;
        shuffle_kernel<<<(int)((total2 + 255) / 256), 256>>>(vf, (__half2*)Xh);
    }
    // operand converts
    {
        long n4 = (long)DT_ * DSHUF / 4;
        cvt_half<<<(int)((n4 + 255) / 256), 256>>>((const float4*)W1w, (__half2*)W1h, n4);
        n4 = (long)V_ * DT_ / 4;
        cvt_half<<<(int)((n4 + 255) / 256), 256>>>((const float4*)W2w, (__half2*)W2h, n4);
        cvt_half<<<(int)((n4 + 255) / 256), 256>>>((const float4*)embed, (__half2*)Eh, n4);
    }

    // 2) F = X @ W1^T            (2048 x 2048, K=4608)
    gemm_h<0,false><<<dim3(MROWS / BM, DT_ / BN), NTH, SMEM_DYN>>>(Xh, W1h, F, nullptr, MROWS, DT_, DSHUF);
    // 3) bias + LN -> half
    ln_kernel<<<MROWS, 256>>>(F, W1b, Fh);
    // 4) Ph = exp(F @ W2^T)      (2048 x 32000, K=2048), half
    gemm_h<1,false><<<dim3(MROWS / BM, V_ / BN), NTH, SMEM_DYN>>>(Fh, W2h, Ph, nullptr, MROWS, V_, DT_);
    // 5) Zinv = 1 / rowsum(Ph)
    rowsum_kernel<<<MROWS, 512>>>((const __half2*)Ph, Zinv);
    // 6) out = (Ph @ Eh) * Zinv[row]   (2048 x 2048, K=32000, NN direct on embed)
    gemm_h<2,true><<<dim3(MROWS / BM, DT_ / BN), NTH, SMEM_DYN>>>(Ph, Eh, out, Zinv, MROWS, DT_, V_);
}

// round 8
// speedup vs baseline: 1.0090x; 1.0090x over previous
#include <cuda_runtime.h>
#include <cuda_fp16.h>
#include <cstdint>
#include <math.h>

// Problem constants
#define B_      8
#define SEQ_    1024
#define DV_     1152
#define DT_     2048
#define V_      32000
#define MROWS   2048
#define DSHUF   4608
#define LN_EPS  1e-5f

// GEMM tiling (fp16 operands): 16 warps, 256x128 CTA tile, 64x32 warp tile
#define BM      256
#define BN      128
#define BKH     64                 // K elems per stage
#define STAGES  3
#define NTH     512
#define ASTG    (BM * 128)         // 32KB: 256 rows x 128B
#define BSTG    (BN * 128)         // 16KB: NT 128 n-rows x 128B; NN 64 k-rows x 256B
#define STGB    (ASTG + BSTG)      // 49152
#define SMEM_DYN (STAGES * STGB)   // 147456

// Scratch (device globals: allocation-guard-safe)
__device__ __half g_Xh [(size_t)MROWS * DSHUF];
__device__ __half g_W1h[(size_t)DT_   * DSHUF];
__device__ float  g_F  [(size_t)MROWS * DT_];
__device__ __half g_Fh [(size_t)MROWS * DT_];
__device__ __half g_W2h[(size_t)V_    * DT_];
__device__ __half g_Eh [(size_t)V_    * DT_];    // embed as half, original [V, DT]
__device__ __half g_Ph [(size_t)MROWS * V_];     // exp(logits), half
__device__ float  g_Zinv[MROWS];

// ---------------------------------------------------------------------------
// helpers
// ---------------------------------------------------------------------------
__device__ __forceinline__ uint32_t smem_u32(const void* p) {
    uint32_t a;
    asm("{ .reg .u64 t; cvta.to.shared.u64 t, %1; cvt.u32.u64 %0, t; }" : "=r"(a) : "l"(p));
    return a;
}
#define CP16(d, s) \
    asm volatile("cp.async.cg.shared.global [%0], [%1], 16;" :: "r"(d), "l"(s))
#define CP_COMMIT()  asm volatile("cp.async.commit_group;")
#define CP_WAIT(n)   asm volatile("cp.async.wait_group %0;" :: "n"(n))

__device__ __forceinline__ void ldsm4(uint32_t& r0, uint32_t& r1, uint32_t& r2,
                                      uint32_t& r3, uint32_t a) {
    asm volatile("ldmatrix.sync.aligned.m8n8.x4.shared.b16 {%0,%1,%2,%3}, [%4];"
                 : "=r"(r0), "=r"(r1), "=r"(r2), "=r"(r3) : "r"(a));
}
__device__ __forceinline__ void ldsm4t(uint32_t& r0, uint32_t& r1, uint32_t& r2,
                                       uint32_t& r3, uint32_t a) {
    asm volatile("ldmatrix.sync.aligned.m8n8.x4.trans.shared.b16 {%0,%1,%2,%3}, [%4];"
                 : "=r"(r0), "=r"(r1), "=r"(r2), "=r"(r3) : "r"(a));
}
__device__ __forceinline__ void mma_f16(float* d, const uint32_t* a,
                                        uint32_t b0, uint32_t b1) {
    asm volatile(
        "mma.sync.aligned.m16n8k16.row.col.f32.f16.f16.f32 "
        "{%0,%1,%2,%3}, {%4,%5,%6,%7}, {%8,%9}, {%0,%1,%2,%3};"
        : "+f"(d[0]), "+f"(d[1]), "+f"(d[2]), "+f"(d[3])
        : "r"(a[0]), "r"(a[1]), "r"(a[2]), "r"(a[3]), "r"(b0), "r"(b1));
}

// ---------------------------------------------------------------------------
// fp16 GEMM, f32 accumulate. 512 threads, 256x128 tile, 64x32 warp tiles,
// BK=64, 3-stage cp.async pipeline, single barrier per iteration.
//   NN=false: C = A[M,K] * B[N,K]^T   (B K-major)
//   NN=true : C = A[M,K] * B[K,N]     (B N-major, ldmatrix.trans fragments)
// MODE: 0 = f32 store; 1 = half(exp(acc)); 2 = f32 * scale[row].
// ---------------------------------------------------------------------------
template<int MODE, bool NN>
__global__ __launch_bounds__(NTH, 1)
void gemm_h(const __half* __restrict__ A, const __half* __restrict__ Bw,
            void* __restrict__ Cv, const float* __restrict__ scale,
            int M, int N, int K)
{
    extern __shared__ __align__(128) char sm[];
    const uint32_t sb = smem_u32(sm);
    const int tid  = threadIdx.x;
    const int warp = tid >> 5;
    const int lane = tid & 31;
    const int gq   = lane >> 2;
    const int tg   = lane & 3;
    const int wm   = (warp & 3) * 64;
    const int wn   = (warp >> 2) * 32;
    const int bm   = blockIdx.x * BM;
    const int bn   = blockIdx.y * BN;
    const int NK   = K / BKH;
    const int rl   = lane & 15;    // ldmatrix row-in-tile
    const int kh   = lane >> 4;    // ldmatrix half-select

    auto load_stage = [&](int f, int slot) {
        const uint32_t sA = sb + (uint32_t)slot * STGB;
        const uint32_t sB = sA + ASTG;
        const __half* Ag = A + (size_t)bm * K + (size_t)f * BKH;
#pragma unroll
        for (int t = 0; t < 4; t++) {            // A: 256 rows x 8 chunks
            int c = tid + t * NTH;
            int row = c >> 3, g = c & 7;
            CP16(sA + row * 128 + ((g ^ (row & 7)) << 4),
                 Ag + (size_t)row * K + g * 8);
        }
        if (!NN) {
            const __half* Bg = Bw + (size_t)bn * K + (size_t)f * BKH;
#pragma unroll
            for (int t = 0; t < 2; t++) {        // B: 128 n-rows x 8 chunks
                int c = tid + t * NTH;
                int row = c >> 3, g = c & 7;
                CP16(sB + row * 128 + ((g ^ (row & 7)) << 4),
                     Bg + (size_t)row * K + g * 8);
            }
        } else {
            const __half* Bg = Bw + (size_t)f * BKH * N + bn;
#pragma unroll
            for (int t = 0; t < 2; t++) {        // B: 64 k-rows x 16 chunks (256B/row)
                int c = tid + t * NTH;
                int krow = c >> 4, ng = c & 15;
                CP16(sB + krow * 256 + ((ng ^ (krow & 7)) << 4),
                     Bg + (size_t)krow * N + ng * 8);
            }
        }
    };

    float acc[4][4][4];
#pragma unroll
    for (int i = 0; i < 4; i++)
#pragma unroll
        for (int j = 0; j < 4; j++)
#pragma unroll
            for (int r = 0; r < 4; r++) acc[i][j][r] = 0.f;

    load_stage(0, 0); CP_COMMIT();
    load_stage(1, 1); CP_COMMIT();

    int slot = 0;
    for (int i = 0; i < NK; i++) {
        CP_WAIT(1);
        __syncthreads();
        // Issue next prefetch BEFORE compute. Safe: write slot == stage i-1's
        // slot, and the barrier above guarantees all warps finished stage i-1.
        {
            const int f = i + STAGES - 1;
            if (f < NK) {
                int ws = slot + STAGES - 1; if (ws >= STAGES) ws -= STAGES;
                load_stage(f, ws);
            }
            CP_COMMIT();             // unconditional: stable group FIFO
        }

        const uint32_t sA = sb + (uint32_t)slot * STGB;
        const uint32_t sB = sA + ASTG;

#pragma unroll
        for (int ks = 0; ks < 4; ks++) {
            uint32_t a[4][4];
            {
                const int g = ks * 2 + kh;
#pragma unroll
                for (int mi = 0; mi < 4; mi++) {
                    int row = wm + mi * 16 + rl;
                    ldsm4(a[mi][0], a[mi][1], a[mi][2], a[mi][3],
                          sA + row * 128 + ((g ^ (row & 7)) << 4));
                }
            }
            uint32_t bf[2][4];
            if (!NN) {
                const int g = ks * 2 + kh;
#pragma unroll
                for (int n2 = 0; n2 < 2; n2++) {
                    int row = wn + n2 * 16 + rl;
                    ldsm4(bf[n2][0], bf[n2][1], bf[n2][2], bf[n2][3],
                          sB + row * 128 + ((g ^ (row & 7)) << 4));
                }
#pragma unroll
                for (int mi = 0; mi < 4; mi++)
#pragma unroll
                    for (int ni = 0; ni < 4; ni++)
                        mma_f16(acc[mi][ni], a[mi],
                                bf[ni >> 1][ni & 1], bf[ni >> 1][(ni & 1) + 2]);
            } else {
                // trans load: each ldsm4t covers 16 k-rows x 16 n-cols.
#pragma unroll
                for (int n2 = 0; n2 < 2; n2++) {
                    int krow = ks * 16 + rl;
                    int ng = ((wn + n2 * 16) >> 3) + kh;
                    ldsm4t(bf[n2][0], bf[n2][1], bf[n2][2], bf[n2][3],
                           sB + krow * 256 + ((ng ^ (krow & 7)) << 4));
                }
                // trans reg order: {n-lo/k-lo, n-lo/k-hi, n-hi/k-lo, n-hi/k-hi}
#pragma unroll
                for (int mi = 0; mi < 4; mi++)
#pragma unroll
                    for (int ni = 0; ni < 4; ni++)
                        mma_f16(acc[mi][ni], a[mi],
                                bf[ni >> 1][(ni & 1) * 2], bf[ni >> 1][(ni & 1) * 2 + 1]);
            }
        }

        if (++slot == STAGES) slot = 0;
    }

    // ---- epilogue ----
#pragma unroll
    for (int mi = 0; mi < 4; mi++) {
        const int r0 = bm + wm + mi * 16 + gq;
#pragma unroll
        for (int ni = 0; ni < 4; ni++) {
            const int c0 = bn + wn + ni * 8 + tg * 2;
            const float* ap = acc[mi][ni];
            if (MODE == 0) {
                float* C = (float*)Cv;
                *(float2*)(C + (size_t)r0 * N + c0)       = make_float2(ap[0], ap[1]);
                *(float2*)(C + (size_t)(r0 + 8) * N + c0) = make_float2(ap[2], ap[3]);
            } else if (MODE == 1) {
                __half2* C = (__half2*)Cv;
                C[((size_t)r0 * N + c0) >> 1] =
                    __floats2half2_rn(__expf(ap[0]), __expf(ap[1]));
                C[((size_t)(r0 + 8) * N + c0) >> 1] =
                    __floats2half2_rn(__expf(ap[2]), __expf(ap[3]));
            } else {
                const float s0 = scale[r0], s1 = scale[r0 + 8];
                float* C = (float*)Cv;
                *(float2*)(C + (size_t)r0 * N + c0)       = make_float2(ap[0] * s0, ap[1] * s0);
                *(float2*)(C + (size_t)(r0 + 8) * N + c0) = make_float2(ap[2] * s1, ap[3] * s1);
            }
        }
    }
}

// ---------------------------------------------------------------------------
// pixel shuffle gather -> half (float2 -> half2)
// ---------------------------------------------------------------------------
__global__ void shuffle_kernel(const float* __restrict__ vf, __half2* __restrict__ X) {
    long i2 = (long)blockIdx.x * blockDim.x + threadIdx.x;
    const long total2 = (long)MROWS * DSHUF / 2;
    if (i2 >= total2) return;
    int e  = (int)(i2 % (DSHUF / 2)) * 2;
    long rl = i2 / (DSHUF / 2);
    int l  = (int)(rl % 256);
    int b  = (int)(rl / 256);
    int d  = e % DV_;
    int h  = 2 * (l >> 4) + (e / (2 * DV_));
    int w  = 2 * (l & 15) + ((e % (2 * DV_)) / DV_);
    float2 v = *(const float2*)(vf + ((long)b * SEQ_ + h * 32 + w) * DV_ + d);
    X[i2] = __floats2half2_rn(v.x, v.y);
}

// ---------------------------------------------------------------------------
// f32 -> half convert copy
// ---------------------------------------------------------------------------
__global__ void cvt_half(const float4* __restrict__ in, __half2* __restrict__ out, long n4) {
    long i = (long)blockIdx.x * blockDim.x + threadIdx.x;
    if (i >= n4) return;
    float4 v = in[i];
    out[2 * i]     = __floats2half2_rn(v.x, v.y);
    out[2 * i + 1] = __floats2half2_rn(v.z, v.w);
}

// ---------------------------------------------------------------------------
// block reduce
// ---------------------------------------------------------------------------
__device__ __forceinline__ float block_reduce_sum(float v) {
    __shared__ float sh[32];
    int lane = threadIdx.x & 31, wid = threadIdx.x >> 5;
#pragma unroll
    for (int o = 16; o > 0; o >>= 1) v += __shfl_xor_sync(0xffffffff, v, o);
    if (lane == 0) sh[wid] = v;
    __syncthreads();
    int nw = blockDim.x >> 5;
    v = (threadIdx.x < nw) ? sh[threadIdx.x] : 0.f;
    if (wid == 0) {
#pragma unroll
        for (int o = 16; o > 0; o >>= 1) v += __shfl_xor_sync(0xffffffff, v, o);
        if (lane == 0) sh[0] = v;
    }
    __syncthreads();
    float r = sh[0];
    __syncthreads();
    return r;
}

// ---------------------------------------------------------------------------
// bias + LayerNorm: F(f32) -> Fh(half)
// ---------------------------------------------------------------------------
__global__ void ln_kernel(const float* __restrict__ F, const float* __restrict__ bias,
                          __half* __restrict__ Fh) {
    const float* p = F + (size_t)blockIdx.x * DT_;
    __half* o = Fh + (size_t)blockIdx.x * DT_;
    float s = 0.f, ss = 0.f;
    for (int i = threadIdx.x; i < DT_; i += blockDim.x) {
        float v = p[i] + bias[i];
        s += v; ss += v * v;
    }
    s  = block_reduce_sum(s);
    ss = block_reduce_sum(ss);
    float mu  = s * (1.0f / DT_);
    float var = ss * (1.0f / DT_) - mu * mu;
    float rstd = rsqrtf(var + LN_EPS);
    for (int i = threadIdx.x; i < DT_; i += blockDim.x)
        o[i] = __float2half_rn((p[i] + bias[i] - mu) * rstd);
}

// ---------------------------------------------------------------------------
// Zinv[r] = 1 / sum(Ph[r,:])   (int4 = 8 halves per load)
// ---------------------------------------------------------------------------
__global__ void rowsum_kernel(const __half* __restrict__ Ph, float* __restrict__ Zinv) {
    const int4* p = (const int4*)(Ph + (size_t)blockIdx.x * V_);
    float s = 0.f;
    for (int i = threadIdx.x; i < V_ / 8; i += blockDim.x) {
        int4 q = p[i];
        const __half2* h = (const __half2*)&q;
#pragma unroll
        for (int j = 0; j < 4; j++) {
            float2 f = __half22float2(h[j]);
            s += f.x + f.y;
        }
    }
    s = block_reduce_sum(s);
    if (threadIdx.x == 0) Zinv[blockIdx.x] = 1.0f / s;
}

// ---------------------------------------------------------------------------
// Launch
// ---------------------------------------------------------------------------
extern "C" void kernel_launch(void* const* d_in, const int* in_sizes, int n_in,
                              void* d_out, int out_size) {
    const float* vf    = (const float*)d_in[0];  // vision_feats
    const float* embed = (const float*)d_in[1];  // llm_token_embed (32000,2048)
    const float* W1w   = (const float*)d_in[2];  // (2048,4608)
    const float* W1b   = (const float*)d_in[3];  // (2048,)
    const float* W2w   = (const float*)d_in[4];  // (32000,2048)
    float* out = (float*)d_out;                  // (8,256,2048) f32

    __half *Xh, *W1h, *Fh, *W2h, *Eh, *Ph;
    float *F, *Zinv;
    cudaGetSymbolAddress((void**)&Xh,   g_Xh);
    cudaGetSymbolAddress((void**)&W1h,  g_W1h);
    cudaGetSymbolAddress((void**)&F,    g_F);
    cudaGetSymbolAddress((void**)&Fh,   g_Fh);
    cudaGetSymbolAddress((void**)&W2h,  g_W2h);
    cudaGetSymbolAddress((void**)&Eh,   g_Eh);
    cudaGetSymbolAddress((void**)&Ph,   g_Ph);
    cudaGetSymbolAddress((void**)&Zinv, g_Zinv);

    cudaFuncSetAttribute(gemm_h<0,false>, cudaFuncAttributeMaxDynamicSharedMemorySize, SMEM_DYN);
    cudaFuncSetAttribute(gemm_h<1,false>, cudaFuncAttributeMaxDynamicSharedMemorySize, SMEM_DYN);
    cudaFuncSetAttribute(gemm_h<2,true>,  cudaFuncAttributeMaxDynamicSharedMemorySize, SMEM_DYN);

    // 1) pixel shuffle -> half
    {
        long total2 = (long)MROWS * DSHUF / 2;
        shuffle_kernel<<<(int)((total2 + 255) / 256), 256>>>(vf, (__half2*)Xh);
    }
    // operand converts
    {
        long n4 = (long)DT_ * DSHUF / 4;
        cvt_half<<<(int)((n4 + 255) / 256), 256>>>((const float4*)W1w, (__half2*)W1h, n4);
        n4 = (long)V_ * DT_ / 4;
        cvt_half<<<(int)((n4 + 255) / 256), 256>>>((const float4*)W2w, (__half2*)W2h, n4);
        cvt_half<<<(int)((n4 + 255) / 256), 256>>>((const float4*)embed, (__half2*)Eh, n4);
    }

    // 2) F = X @ W1^T            (2048 x 2048, K=4608)
    gemm_h<0,false><<<dim3(MROWS / BM, DT_ / BN), NTH, SMEM_DYN>>>(Xh, W1h, F, nullptr, MROWS, DT_, DSHUF);
    // 3) bias + LN -> half
    ln_kernel<<<MROWS, 256>>>(F, W1b, Fh);
    // 4) Ph = exp(F @ W2^T)      (2048 x 32000, K=2048), half
    gemm_h<1,false><<<dim3(MROWS / BM, V_ / BN), NTH, SMEM_DYN>>>(Fh, W2h, Ph, nullptr, MROWS, V_, DT_);
    // 5) Zinv = 1 / rowsum(Ph)
    rowsum_kernel<<<MROWS, 512>>>(Ph, Zinv);
    // 6) out = (Ph @ Eh) * Zinv[row]   (2048 x 2048, K=32000, NN direct on embed)
    gemm_h<2,true><<<dim3(MROWS / BM, DT_ / BN), NTH, SMEM_DYN>>>(Ph, Eh, out, Zinv, MROWS, DT_, V_);
}

// round 9
// speedup vs baseline: 1.0716x; 1.0620x over previous
#include <cuda_runtime.h>
#include <cuda_fp16.h>
#include <cstdint>
#include <math.h>

// Problem constants
#define B_      8
#define SEQ_    1024
#define DV_     1152
#define DT_     2048
#define V_      32000
#define MROWS   2048
#define DSHUF   4608
#define LN_EPS  1e-5f

// GEMM tiling: 8 warps, 128x128 CTA tile, 64x32 warp tile, 2 CTAs/SM
#define BM      128
#define BN      128
#define BKH     64                 // K elems per stage
#define STAGES  3
#define NTH     256
#define ASTG    (BM * 128)         // 16KB
#define BSTG    (BN * 128)         // 16KB (NT: 128 n-rows x 128B; NN: 64 k-rows x 256B)
#define STGB    (ASTG + BSTG)      // 32768
#define SMEM_DYN (STAGES * STGB)   // 98304

// Scratch (device globals: allocation-guard-safe)
__device__ __half g_Xh [(size_t)MROWS * DSHUF];
__device__ __half g_W1h[(size_t)DT_   * DSHUF];
__device__ float  g_F  [(size_t)MROWS * DT_];
__device__ __half g_Fh [(size_t)MROWS * DT_];
__device__ __half g_W2h[(size_t)V_    * DT_];
__device__ __half g_Eh [(size_t)V_    * DT_];    // embed as half, original [V, DT]
__device__ __half g_Ph [(size_t)MROWS * V_];     // exp(logits), half
__device__ float  g_Zinv[MROWS];

// ---------------------------------------------------------------------------
// helpers
// ---------------------------------------------------------------------------
__device__ __forceinline__ uint32_t smem_u32(const void* p) {
    uint32_t a;
    asm("{ .reg .u64 t; cvta.to.shared.u64 t, %1; cvt.u32.u64 %0, t; }" : "=r"(a) : "l"(p));
    return a;
}
#define CP16(d, s) \
    asm volatile("cp.async.cg.shared.global [%0], [%1], 16;" :: "r"(d), "l"(s))
#define CP_COMMIT()  asm volatile("cp.async.commit_group;")
#define CP_WAIT(n)   asm volatile("cp.async.wait_group %0;" :: "n"(n))

__device__ __forceinline__ void ldsm4(uint32_t& r0, uint32_t& r1, uint32_t& r2,
                                      uint32_t& r3, uint32_t a) {
    asm volatile("ldmatrix.sync.aligned.m8n8.x4.shared.b16 {%0,%1,%2,%3}, [%4];"
                 : "=r"(r0), "=r"(r1), "=r"(r2), "=r"(r3) : "r"(a));
}
__device__ __forceinline__ void ldsm4t(uint32_t& r0, uint32_t& r1, uint32_t& r2,
                                       uint32_t& r3, uint32_t a) {
    asm volatile("ldmatrix.sync.aligned.m8n8.x4.trans.shared.b16 {%0,%1,%2,%3}, [%4];"
                 : "=r"(r0), "=r"(r1), "=r"(r2), "=r"(r3) : "r"(a));
}
__device__ __forceinline__ void mma_f16(float* d, const uint32_t* a,
                                        uint32_t b0, uint32_t b1) {
    asm volatile(
        "mma.sync.aligned.m16n8k16.row.col.f32.f16.f16.f32 "
        "{%0,%1,%2,%3}, {%4,%5,%6,%7}, {%8,%9}, {%0,%1,%2,%3};"
        : "+f"(d[0]), "+f"(d[1]), "+f"(d[2]), "+f"(d[3])
        : "r"(a[0]), "r"(a[1]), "r"(a[2]), "r"(a[3]), "r"(b0), "r"(b1));
}

// ---------------------------------------------------------------------------
// fp16 GEMM, f32 accumulate. 256 threads, 128x128 tile, 64x32 warp tiles,
// BK=64, 3-stage cp.async pipeline, 2 CTAs resident per SM.
//   NN=false: C = A[M,K] * B[N,K]^T   (B K-major)
//   NN=true : C = A[M,K] * B[K,N]     (B N-major, ldmatrix.trans fragments)
// MODE: 0 = f32 store; 1 = half(exp(acc)); 2 = f32 * scale[row].
// ---------------------------------------------------------------------------
template<int MODE, bool NN>
__global__ __launch_bounds__(NTH, 2)
void gemm_h(const __half* __restrict__ A, const __half* __restrict__ Bw,
            void* __restrict__ Cv, const float* __restrict__ scale,
            int M, int N, int K)
{
    extern __shared__ __align__(128) char sm[];
    const uint32_t sb = smem_u32(sm);
    const int tid  = threadIdx.x;
    const int warp = tid >> 5;
    const int lane = tid & 31;
    const int gq   = lane >> 2;
    const int tg   = lane & 3;
    const int wm   = (warp & 1) * 64;     // 2 warps in m
    const int wn   = (warp >> 1) * 32;    // 4 warps in n
    const int bm   = blockIdx.x * BM;
    const int bn   = blockIdx.y * BN;
    const int NK   = K / BKH;
    const int rl   = lane & 15;    // ldmatrix row-in-tile
    const int kh   = lane >> 4;    // ldmatrix half-select

    auto load_stage = [&](int f, int slot) {
        const uint32_t sA = sb + (uint32_t)slot * STGB;
        const uint32_t sB = sA + ASTG;
        const __half* Ag = A + (size_t)bm * K + (size_t)f * BKH;
#pragma unroll
        for (int t = 0; t < 4; t++) {            // A: 128 rows x 8 chunks
            int c = tid + t * NTH;
            int row = c >> 3, g = c & 7;
            CP16(sA + row * 128 + ((g ^ (row & 7)) << 4),
                 Ag + (size_t)row * K + g * 8);
        }
        if (!NN) {
            const __half* Bg = Bw + (size_t)bn * K + (size_t)f * BKH;
#pragma unroll
            for (int t = 0; t < 4; t++) {        // B: 128 n-rows x 8 chunks
                int c = tid + t * NTH;
                int row = c >> 3, g = c & 7;
                CP16(sB + row * 128 + ((g ^ (row & 7)) << 4),
                     Bg + (size_t)row * K + g * 8);
            }
        } else {
            const __half* Bg = Bw + (size_t)f * BKH * N + bn;
#pragma unroll
            for (int t = 0; t < 4; t++) {        // B: 64 k-rows x 16 chunks (256B/row)
                int c = tid + t * NTH;
                int krow = c >> 4, ng = c & 15;
                CP16(sB + krow * 256 + ((ng ^ (krow & 7)) << 4),
                     Bg + (size_t)krow * N + ng * 8);
            }
        }
    };

    float acc[4][4][4];
#pragma unroll
    for (int i = 0; i < 4; i++)
#pragma unroll
        for (int j = 0; j < 4; j++)
#pragma unroll
            for (int r = 0; r < 4; r++) acc[i][j][r] = 0.f;

    load_stage(0, 0); CP_COMMIT();
    load_stage(1, 1); CP_COMMIT();

    int slot = 0;
    for (int i = 0; i < NK; i++) {
        CP_WAIT(1);
        __syncthreads();

        const uint32_t sA = sb + (uint32_t)slot * STGB;
        const uint32_t sB = sA + ASTG;

#pragma unroll
        for (int ks = 0; ks < 4; ks++) {
            uint32_t a[4][4];
            {
                const int g = ks * 2 + kh;
#pragma unroll
                for (int mi = 0; mi < 4; mi++) {
                    int row = wm + mi * 16 + rl;
                    ldsm4(a[mi][0], a[mi][1], a[mi][2], a[mi][3],
                          sA + row * 128 + ((g ^ (row & 7)) << 4));
                }
            }
            uint32_t bf[2][4];
            if (!NN) {
                const int g = ks * 2 + kh;
#pragma unroll
                for (int n2 = 0; n2 < 2; n2++) {
                    int row = wn + n2 * 16 + rl;
                    ldsm4(bf[n2][0], bf[n2][1], bf[n2][2], bf[n2][3],
                          sB + row * 128 + ((g ^ (row & 7)) << 4));
                }
#pragma unroll
                for (int mi = 0; mi < 4; mi++)
#pragma unroll
                    for (int ni = 0; ni < 4; ni++)
                        mma_f16(acc[mi][ni], a[mi],
                                bf[ni >> 1][ni & 1], bf[ni >> 1][(ni & 1) + 2]);
            } else {
                // trans load: each ldsm4t covers 16 k-rows x 16 n-cols.
#pragma unroll
                for (int n2 = 0; n2 < 2; n2++) {
                    int krow = ks * 16 + rl;
                    int ng = ((wn + n2 * 16) >> 3) + kh;
                    ldsm4t(bf[n2][0], bf[n2][1], bf[n2][2], bf[n2][3],
                           sB + krow * 256 + ((ng ^ (krow & 7)) << 4));
                }
                // trans reg order: {n-lo/k-lo, n-lo/k-hi, n-hi/k-lo, n-hi/k-hi}
#pragma unroll
                for (int mi = 0; mi < 4; mi++)
#pragma unroll
                    for (int ni = 0; ni < 4; ni++)
                        mma_f16(acc[mi][ni], a[mi],
                                bf[ni >> 1][(ni & 1) * 2], bf[ni >> 1][(ni & 1) * 2 + 1]);
            }
        }
        __syncthreads();

        const int f = i + STAGES - 1;
        if (f < NK) {
            int ws = slot + STAGES - 1; if (ws >= STAGES) ws -= STAGES;
            load_stage(f, ws);
        }
        CP_COMMIT();                 // unconditional: stable group FIFO
        if (++slot == STAGES) slot = 0;
    }

    // ---- epilogue ----
#pragma unroll
    for (int mi = 0; mi < 4; mi++) {
        const int r0 = bm + wm + mi * 16 + gq;
#pragma unroll
        for (int ni = 0; ni < 4; ni++) {
            const int c0 = bn + wn + ni * 8 + tg * 2;
            const float* ap = acc[mi][ni];
            if (MODE == 0) {
                float* C = (float*)Cv;
                *(float2*)(C + (size_t)r0 * N + c0)       = make_float2(ap[0], ap[1]);
                *(float2*)(C + (size_t)(r0 + 8) * N + c0) = make_float2(ap[2], ap[3]);
            } else if (MODE == 1) {
                __half2* C = (__half2*)Cv;
                C[((size_t)r0 * N + c0) >> 1] =
                    __floats2half2_rn(__expf(ap[0]), __expf(ap[1]));
                C[((size_t)(r0 + 8) * N + c0) >> 1] =
                    __floats2half2_rn(__expf(ap[2]), __expf(ap[3]));
            } else {
                const float s0 = scale[r0], s1 = scale[r0 + 8];
                float* C = (float*)Cv;
                *(float2*)(C + (size_t)r0 * N + c0)       = make_float2(ap[0] * s0, ap[1] * s0);
                *(float2*)(C + (size_t)(r0 + 8) * N + c0) = make_float2(ap[2] * s1, ap[3] * s1);
            }
        }
    }
}

// ---------------------------------------------------------------------------
// pixel shuffle gather -> half (float2 -> half2)
// ---------------------------------------------------------------------------
__global__ void shuffle_kernel(const float* __restrict__ vf, __half2* __restrict__ X) {
    long i2 = (long)blockIdx.x * blockDim.x + threadIdx.x;
    const long total2 = (long)MROWS * DSHUF / 2;
    if (i2 >= total2) return;
    int e  = (int)(i2 % (DSHUF / 2)) * 2;
    long rl = i2 / (DSHUF / 2);
    int l  = (int)(rl % 256);
    int b  = (int)(rl / 256);
    int d  = e % DV_;
    int h  = 2 * (l >> 4) + (e / (2 * DV_));
    int w  = 2 * (l & 15) + ((e % (2 * DV_)) / DV_);
    float2 v = *(const float2*)(vf + ((long)b * SEQ_ + h * 32 + w) * DV_ + d);
    X[i2] = __floats2half2_rn(v.x, v.y);
}

// ---------------------------------------------------------------------------
// f32 -> half convert copy
// ---------------------------------------------------------------------------
__global__ void cvt_half(const float4* __restrict__ in, __half2* __restrict__ out, long n4) {
    long i = (long)blockIdx.x * blockDim.x + threadIdx.x;
    if (i >= n4) return;
    float4 v = in[i];
    out[2 * i]     = __floats2half2_rn(v.x, v.y);
    out[2 * i + 1] = __floats2half2_rn(v.z, v.w);
}

// ---------------------------------------------------------------------------
// block reduce
// ---------------------------------------------------------------------------
__device__ __forceinline__ float block_reduce_sum(float v) {
    __shared__ float sh[32];
    int lane = threadIdx.x & 31, wid = threadIdx.x >> 5;
#pragma unroll
    for (int o = 16; o > 0; o >>= 1) v += __shfl_xor_sync(0xffffffff, v, o);
    if (lane == 0) sh[wid] = v;
    __syncthreads();
    int nw = blockDim.x >> 5;
    v = (threadIdx.x < nw) ? sh[threadIdx.x] : 0.f;
    if (wid == 0) {
#pragma unroll
        for (int o = 16; o > 0; o >>= 1) v += __shfl_xor_sync(0xffffffff, v, o);
        if (lane == 0) sh[0] = v;
    }
    __syncthreads();
    float r = sh[0];
    __syncthreads();
    return r;
}

// ---------------------------------------------------------------------------
// bias + LayerNorm: F(f32) -> Fh(half)
// ---------------------------------------------------------------------------
__global__ void ln_kernel(const float* __restrict__ F, const float* __restrict__ bias,
                          __half* __restrict__ Fh) {
    const float* p = F + (size_t)blockIdx.x * DT_;
    __half* o = Fh + (size_t)blockIdx.x * DT_;
    float s = 0.f, ss = 0.f;
    for (int i = threadIdx.x; i < DT_; i += blockDim.x) {
        float v = p[i] + bias[i];
        s += v; ss += v * v;
    }
    s  = block_reduce_sum(s);
    ss = block_reduce_sum(ss);
    float mu  = s * (1.0f / DT_);
    float var = ss * (1.0f / DT_) - mu * mu;
    float rstd = rsqrtf(var + LN_EPS);
    for (int i = threadIdx.x; i < DT_; i += blockDim.x)
        o[i] = __float2half_rn((p[i] + bias[i] - mu) * rstd);
}

// ---------------------------------------------------------------------------
// Zinv[r] = 1 / sum(Ph[r,:])   (int4 = 8 halves per load)
// ---------------------------------------------------------------------------
__global__ void rowsum_kernel(const __half* __restrict__ Ph, float* __restrict__ Zinv) {
    const int4* p = (const int4*)(Ph + (size_t)blockIdx.x * V_);
    float s = 0.f;
    for (int i = threadIdx.x; i < V_ / 8; i += blockDim.x) {
        int4 q = p[i];
        const __half2* h = (const __half2*)&q;
#pragma unroll
        for (int j = 0; j < 4; j++) {
            float2 f = __half22float2(h[j]);
            s += f.x + f.y;
        }
    }
    s = block_reduce_sum(s);
    if (threadIdx.x == 0) Zinv[blockIdx.x] = 1.0f / s;
}

// ---------------------------------------------------------------------------
// Launch
// ---------------------------------------------------------------------------
extern "C" void kernel_launch(void* const* d_in, const int* in_sizes, int n_in,
                              void* d_out, int out_size) {
    const float* vf    = (const float*)d_in[0];  // vision_feats
    const float* embed = (const float*)d_in[1];  // llm_token_embed (32000,2048)
    const float* W1w   = (const float*)d_in[2];  // (2048,4608)
    const float* W1b   = (const float*)d_in[3];  // (2048,)
    const float* W2w   = (const float*)d_in[4];  // (32000,2048)
    float* out = (float*)d_out;                  // (8,256,2048) f32

    __half *Xh, *W1h, *Fh, *W2h, *Eh, *Ph;
    float *F, *Zinv;
    cudaGetSymbolAddress((void**)&Xh,   g_Xh);
    cudaGetSymbolAddress((void**)&W1h,  g_W1h);
    cudaGetSymbolAddress((void**)&F,    g_F);
    cudaGetSymbolAddress((void**)&Fh,   g_Fh);
    cudaGetSymbolAddress((void**)&W2h,  g_W2h);
    cudaGetSymbolAddress((void**)&Eh,   g_Eh);
    cudaGetSymbolAddress((void**)&Ph,   g_Ph);
    cudaGetSymbolAddress((void**)&Zinv, g_Zinv);

    cudaFuncSetAttribute(gemm_h<0,false>, cudaFuncAttributeMaxDynamicSharedMemorySize, SMEM_DYN);
    cudaFuncSetAttribute(gemm_h<1,false>, cudaFuncAttributeMaxDynamicSharedMemorySize, SMEM_DYN);
    cudaFuncSetAttribute(gemm_h<2,true>,  cudaFuncAttributeMaxDynamicSharedMemorySize, SMEM_DYN);

    // 1) pixel shuffle -> half
    {
        long total2 = (long)MROWS * DSHUF / 2;
        shuffle_kernel<<<(int)((total2 + 255) / 256), 256>>>(vf, (__half2*)Xh);
    }
    // operand converts
    {
        long n4 = (long)DT_ * DSHUF / 4;
        cvt_half<<<(int)((n4 + 255) / 256), 256>>>((const float4*)W1w, (__half2*)W1h, n4);
        n4 = (long)V_ * DT_ / 4;
        cvt_half<<<(int)((n4 + 255) / 256), 256>>>((const float4*)W2w, (__half2*)W2h, n4);
        cvt_half<<<(int)((n4 + 255) / 256), 256>>>((const float4*)embed, (__half2*)Eh, n4);
    }

    // 2) F = X @ W1^T            (2048 x 2048, K=4608)
    gemm_h<0,false><<<dim3(MROWS / BM, DT_ / BN), NTH, SMEM_DYN>>>(Xh, W1h, F, nullptr, MROWS, DT_, DSHUF);
    // 3) bias + LN -> half
    ln_kernel<<<MROWS, 256>>>(F, W1b, Fh);
    // 4) Ph = exp(F @ W2^T)      (2048 x 32000, K=2048), half
    gemm_h<1,false><<<dim3(MROWS / BM, V_ / BN), NTH, SMEM_DYN>>>(Fh, W2h, Ph, nullptr, MROWS, V_, DT_);
    // 5) Zinv = 1 / rowsum(Ph)
    rowsum_kernel<<<MROWS, 512>>>(Ph, Zinv);
    // 6) out = (Ph @ Eh) * Zinv[row]   (2048 x 2048, K=32000, NN direct on embed)
    gemm_h<2,true><<<dim3(MROWS / BM, DT_ / BN), NTH, SMEM_DYN>>>(Ph, Eh, out, Zinv, MROWS, DT_, V_);
}

// round 10
// speedup vs baseline: 1.1027x; 1.0290x over previous
#include <cuda_runtime.h>
#include <cuda_fp16.h>
#include <cstdint>
#include <math.h>

// Problem constants
#define B_      8
#define SEQ_    1024
#define DV_     1152
#define DT_     2048
#define V_      32000
#define MROWS   2048
#define DSHUF   4608
#define LN_EPS  1e-5f

// GEMM tiling: 8 warps, 128x128 CTA tile, 64x32 warp tile, 2 CTAs/SM
#define BM      128
#define BN      128
#define BKH     64                 // K elems per stage
#define STAGES  3
#define NTH     256
#define ASTG    (BM * 128)         // 16KB
#define BSTG    (BN * 128)         // 16KB (NT: 128 n-rows x 128B; NN: 64 k-rows x 256B)
#define STGB    (ASTG + BSTG)      // 32768
#define SMEM_DYN (STAGES * STGB)   // 98304

// Scratch (device globals: allocation-guard-safe)
__device__ __half g_Xh [(size_t)MROWS * DSHUF];
__device__ __half g_W1h[(size_t)DT_   * DSHUF];
__device__ float  g_F  [(size_t)MROWS * DT_];
__device__ __half g_Fh [(size_t)MROWS * DT_];
__device__ __half g_W2h[(size_t)V_    * DT_];
__device__ __half g_Eh [(size_t)V_    * DT_];    // embed as half, original [V, DT]
__device__ __half g_Ph [(size_t)MROWS * V_];     // exp(logits), half
__device__ float  g_Zinv[MROWS];

// ---------------------------------------------------------------------------
// helpers
// ---------------------------------------------------------------------------
__device__ __forceinline__ uint32_t smem_u32(const void* p) {
    uint32_t a;
    asm("{ .reg .u64 t; cvta.to.shared.u64 t, %1; cvt.u32.u64 %0, t; }" : "=r"(a) : "l"(p));
    return a;
}
#define CP16(d, s) \
    asm volatile("cp.async.cg.shared.global [%0], [%1], 16;" :: "r"(d), "l"(s))
#define CP_COMMIT()  asm volatile("cp.async.commit_group;")
#define CP_WAIT(n)   asm volatile("cp.async.wait_group %0;" :: "n"(n))

__device__ __forceinline__ void ldsm4(uint32_t& r0, uint32_t& r1, uint32_t& r2,
                                      uint32_t& r3, uint32_t a) {
    asm volatile("ldmatrix.sync.aligned.m8n8.x4.shared.b16 {%0,%1,%2,%3}, [%4];"
                 : "=r"(r0), "=r"(r1), "=r"(r2), "=r"(r3) : "r"(a));
}
__device__ __forceinline__ void ldsm4t(uint32_t& r0, uint32_t& r1, uint32_t& r2,
                                       uint32_t& r3, uint32_t a) {
    asm volatile("ldmatrix.sync.aligned.m8n8.x4.trans.shared.b16 {%0,%1,%2,%3}, [%4];"
                 : "=r"(r0), "=r"(r1), "=r"(r2), "=r"(r3) : "r"(a));
}
__device__ __forceinline__ void mma_f16(float* d, const uint32_t* a,
                                        uint32_t b0, uint32_t b1) {
    asm volatile(
        "mma.sync.aligned.m16n8k16.row.col.f32.f16.f16.f32 "
        "{%0,%1,%2,%3}, {%4,%5,%6,%7}, {%8,%9}, {%0,%1,%2,%3};"
        : "+f"(d[0]), "+f"(d[1]), "+f"(d[2]), "+f"(d[3])
        : "r"(a[0]), "r"(a[1]), "r"(a[2]), "r"(a[3]), "r"(b0), "r"(b1));
}

// ---------------------------------------------------------------------------
// fp16 GEMM, f32 accumulate. 256 threads, 128x128 tile, 64x32 warp tiles,
// BK=64, 3-stage cp.async pipeline, 2 CTAs resident per SM.
//   NN=false: C = A[M,K] * B[N,K]^T   (B K-major)
//   NN=true : C = A[M,K] * B[K,N]     (B N-major, ldmatrix.trans fragments)
// MODE: 0 = f32 store; 1 = half(exp(acc)); 2 = f32 * scale[row].
// Fused f32->f16 converter (cvt_src/cvt_dst/cvt_n4):
//   MODE 0: extra CTAs (blockIdx.y >= N/BN) are pure converters running
//           concurrently with the compute CTAs (GEMM1 grid is <1 wave).
//   MODE 1: every CTA converts its grid-stride slice after its epilogue,
//           overlapped with later waves' compute (GEMM2 has ~13 waves).
// ---------------------------------------------------------------------------
template<int MODE, bool NN>
__global__ __launch_bounds__(NTH, 2)
void gemm_h(const __half* __restrict__ A, const __half* __restrict__ Bw,
            void* __restrict__ Cv, const float* __restrict__ scale,
            int M, int N, int K,
            const float4* __restrict__ cvt_src, __half2* __restrict__ cvt_dst,
            long cvt_n4)
{
    extern __shared__ __align__(128) char sm[];
    const uint32_t sb = smem_u32(sm);
    const int tid  = threadIdx.x;

    if (MODE == 0 && cvt_src && blockIdx.y >= (unsigned)(N / BN)) {
        // pure converter CTA (concurrent with compute CTAs)
        const long nconv = (long)(gridDim.y - N / BN) * gridDim.x;
        long base   = ((long)(blockIdx.y - N / BN) * gridDim.x + blockIdx.x) * NTH + tid;
        long stride = nconv * NTH;
        for (long i = base; i < cvt_n4; i += stride) {
            float4 v = cvt_src[i];
            cvt_dst[2 * i]     = __floats2half2_rn(v.x, v.y);
            cvt_dst[2 * i + 1] = __floats2half2_rn(v.z, v.w);
        }
        return;
    }

    const int warp = tid >> 5;
    const int lane = tid & 31;
    const int gq   = lane >> 2;
    const int tg   = lane & 3;
    const int wm   = (warp & 1) * 64;     // 2 warps in m
    const int wn   = (warp >> 1) * 32;    // 4 warps in n
    const int bm   = blockIdx.x * BM;
    const int bn   = blockIdx.y * BN;
    const int NK   = K / BKH;
    const int rl   = lane & 15;    // ldmatrix row-in-tile
    const int kh   = lane >> 4;    // ldmatrix half-select

    auto load_stage = [&](int f, int slot) {
        const uint32_t sA = sb + (uint32_t)slot * STGB;
        const uint32_t sB = sA + ASTG;
        const __half* Ag = A + (size_t)bm * K + (size_t)f * BKH;
#pragma unroll
        for (int t = 0; t < 4; t++) {            // A: 128 rows x 8 chunks
            int c = tid + t * NTH;
            int row = c >> 3, g = c & 7;
            CP16(sA + row * 128 + ((g ^ (row & 7)) << 4),
                 Ag + (size_t)row * K + g * 8);
        }
        if (!NN) {
            const __half* Bg = Bw + (size_t)bn * K + (size_t)f * BKH;
#pragma unroll
            for (int t = 0; t < 4; t++) {        // B: 128 n-rows x 8 chunks
                int c = tid + t * NTH;
                int row = c >> 3, g = c & 7;
                CP16(sB + row * 128 + ((g ^ (row & 7)) << 4),
                     Bg + (size_t)row * K + g * 8);
            }
        } else {
            const __half* Bg = Bw + (size_t)f * BKH * N + bn;
#pragma unroll
            for (int t = 0; t < 4; t++) {        // B: 64 k-rows x 16 chunks (256B/row)
                int c = tid + t * NTH;
                int krow = c >> 4, ng = c & 15;
                CP16(sB + krow * 256 + ((ng ^ (krow & 7)) << 4),
                     Bg + (size_t)krow * N + ng * 8);
            }
        }
    };

    float acc[4][4][4];
#pragma unroll
    for (int i = 0; i < 4; i++)
#pragma unroll
        for (int j = 0; j < 4; j++)
#pragma unroll
            for (int r = 0; r < 4; r++) acc[i][j][r] = 0.f;

    load_stage(0, 0); CP_COMMIT();
    load_stage(1, 1); CP_COMMIT();

    int slot = 0;
    for (int i = 0; i < NK; i++) {
        CP_WAIT(1);
        __syncthreads();

        const uint32_t sA = sb + (uint32_t)slot * STGB;
        const uint32_t sB = sA + ASTG;

#pragma unroll
        for (int ks = 0; ks < 4; ks++) {
            uint32_t a[4][4];
            {
                const int g = ks * 2 + kh;
#pragma unroll
                for (int mi = 0; mi < 4; mi++) {
                    int row = wm + mi * 16 + rl;
                    ldsm4(a[mi][0], a[mi][1], a[mi][2], a[mi][3],
                          sA + row * 128 + ((g ^ (row & 7)) << 4));
                }
            }
            uint32_t bf[2][4];
            if (!NN) {
                const int g = ks * 2 + kh;
#pragma unroll
                for (int n2 = 0; n2 < 2; n2++) {
                    int row = wn + n2 * 16 + rl;
                    ldsm4(bf[n2][0], bf[n2][1], bf[n2][2], bf[n2][3],
                          sB + row * 128 + ((g ^ (row & 7)) << 4));
                }
#pragma unroll
                for (int mi = 0; mi < 4; mi++)
#pragma unroll
                    for (int ni = 0; ni < 4; ni++)
                        mma_f16(acc[mi][ni], a[mi],
                                bf[ni >> 1][ni & 1], bf[ni >> 1][(ni & 1) + 2]);
            } else {
                // trans load: each ldsm4t covers 16 k-rows x 16 n-cols.
#pragma unroll
                for (int n2 = 0; n2 < 2; n2++) {
                    int krow = ks * 16 + rl;
                    int ng = ((wn + n2 * 16) >> 3) + kh;
                    ldsm4t(bf[n2][0], bf[n2][1], bf[n2][2], bf[n2][3],
                           sB + krow * 256 + ((ng ^ (krow & 7)) << 4));
                }
                // trans reg order: {n-lo/k-lo, n-lo/k-hi, n-hi/k-lo, n-hi/k-hi}
#pragma unroll
                for (int mi = 0; mi < 4; mi++)
#pragma unroll
                    for (int ni = 0; ni < 4; ni++)
                        mma_f16(acc[mi][ni], a[mi],
                                bf[ni >> 1][(ni & 1) * 2], bf[ni >> 1][(ni & 1) * 2 + 1]);
            }
        }
        __syncthreads();

        const int f = i + STAGES - 1;
        if (f < NK) {
            int ws = slot + STAGES - 1; if (ws >= STAGES) ws -= STAGES;
            load_stage(f, ws);
        }
        CP_COMMIT();                 // unconditional: stable group FIFO
        if (++slot == STAGES) slot = 0;
    }

    // ---- epilogue ----
#pragma unroll
    for (int mi = 0; mi < 4; mi++) {
        const int r0 = bm + wm + mi * 16 + gq;
#pragma unroll
        for (int ni = 0; ni < 4; ni++) {
            const int c0 = bn + wn + ni * 8 + tg * 2;
            const float* ap = acc[mi][ni];
            if (MODE == 0) {
                float* C = (float*)Cv;
                *(float2*)(C + (size_t)r0 * N + c0)       = make_float2(ap[0], ap[1]);
                *(float2*)(C + (size_t)(r0 + 8) * N + c0) = make_float2(ap[2], ap[3]);
            } else if (MODE == 1) {
                __half2* C = (__half2*)Cv;
                C[((size_t)r0 * N + c0) >> 1] =
                    __floats2half2_rn(__expf(ap[0]), __expf(ap[1]));
                C[((size_t)(r0 + 8) * N + c0) >> 1] =
                    __floats2half2_rn(__expf(ap[2]), __expf(ap[3]));
            } else {
                const float s0 = scale[r0], s1 = scale[r0 + 8];
                float* C = (float*)Cv;
                *(float2*)(C + (size_t)r0 * N + c0)       = make_float2(ap[0] * s0, ap[1] * s0);
                *(float2*)(C + (size_t)(r0 + 8) * N + c0) = make_float2(ap[2] * s1, ap[3] * s1);
            }
        }
    }

    // ---- fused converter slice (MODE 1: overlaps with later waves) ----
    if (MODE == 1 && cvt_src) {
        const long ncta = (long)gridDim.x * gridDim.y;
        long base   = ((long)blockIdx.y * gridDim.x + blockIdx.x) * NTH + tid;
        long stride = ncta * NTH;
        for (long i = base; i < cvt_n4; i += stride) {
            float4 v = cvt_src[i];
            cvt_dst[2 * i]     = __floats2half2_rn(v.x, v.y);
            cvt_dst[2 * i + 1] = __floats2half2_rn(v.z, v.w);
        }
    }
}

// ---------------------------------------------------------------------------
// pixel shuffle gather -> half (float2 -> half2)
// ---------------------------------------------------------------------------
__global__ void shuffle_kernel(const float* __restrict__ vf, __half2* __restrict__ X) {
    long i2 = (long)blockIdx.x * blockDim.x + threadIdx.x;
    const long total2 = (long)MROWS * DSHUF / 2;
    if (i2 >= total2) return;
    int e  = (int)(i2 % (DSHUF / 2)) * 2;
    long rl = i2 / (DSHUF / 2);
    int l  = (int)(rl % 256);
    int b  = (int)(rl / 256);
    int d  = e % DV_;
    int h  = 2 * (l >> 4) + (e / (2 * DV_));
    int w  = 2 * (l & 15) + ((e % (2 * DV_)) / DV_);
    float2 v = *(const float2*)(vf + ((long)b * SEQ_ + h * 32 + w) * DV_ + d);
    X[i2] = __floats2half2_rn(v.x, v.y);
}

// ---------------------------------------------------------------------------
// f32 -> half convert copy (still used for W1)
// ---------------------------------------------------------------------------
__global__ void cvt_half(const float4* __restrict__ in, __half2* __restrict__ out, long n4) {
    long i = (long)blockIdx.x * blockDim.x + threadIdx.x;
    if (i >= n4) return;
    float4 v = in[i];
    out[2 * i]     = __floats2half2_rn(v.x, v.y);
    out[2 * i + 1] = __floats2half2_rn(v.z, v.w);
}

// ---------------------------------------------------------------------------
// block reduce
// ---------------------------------------------------------------------------
__device__ __forceinline__ float block_reduce_sum(float v) {
    __shared__ float sh[32];
    int lane = threadIdx.x & 31, wid = threadIdx.x >> 5;
#pragma unroll
    for (int o = 16; o > 0; o >>= 1) v += __shfl_xor_sync(0xffffffff, v, o);
    if (lane == 0) sh[wid] = v;
    __syncthreads();
    int nw = blockDim.x >> 5;
    v = (threadIdx.x < nw) ? sh[threadIdx.x] : 0.f;
    if (wid == 0) {
#pragma unroll
        for (int o = 16; o > 0; o >>= 1) v += __shfl_xor_sync(0xffffffff, v, o);
        if (lane == 0) sh[0] = v;
    }
    __syncthreads();
    float r = sh[0];
    __syncthreads();
    return r;
}

// ---------------------------------------------------------------------------
// bias + LayerNorm: F(f32) -> Fh(half)
// ---------------------------------------------------------------------------
__global__ void ln_kernel(const float* __restrict__ F, const float* __restrict__ bias,
                          __half* __restrict__ Fh) {
    const float* p = F + (size_t)blockIdx.x * DT_;
    __half* o = Fh + (size_t)blockIdx.x * DT_;
    float s = 0.f, ss = 0.f;
    for (int i = threadIdx.x; i < DT_; i += blockDim.x) {
        float v = p[i] + bias[i];
        s += v; ss += v * v;
    }
    s  = block_reduce_sum(s);
    ss = block_reduce_sum(ss);
    float mu  = s * (1.0f / DT_);
    float var = ss * (1.0f / DT_) - mu * mu;
    float rstd = rsqrtf(var + LN_EPS);
    for (int i = threadIdx.x; i < DT_; i += blockDim.x)
        o[i] = __float2half_rn((p[i] + bias[i] - mu) * rstd);
}

// ---------------------------------------------------------------------------
// Zinv[r] = 1 / sum(Ph[r,:])   (int4 = 8 halves per load)
// ---------------------------------------------------------------------------
__global__ void rowsum_kernel(const __half* __restrict__ Ph, float* __restrict__ Zinv) {
    const int4* p = (const int4*)(Ph + (size_t)blockIdx.x * V_);
    float s = 0.f;
    for (int i = threadIdx.x; i < V_ / 8; i += blockDim.x) {
        int4 q = p[i];
        const __half2* h = (const __half2*)&q;
#pragma unroll
        for (int j = 0; j < 4; j++) {
            float2 f = __half22float2(h[j]);
            s += f.x + f.y;
        }
    }
    s = block_reduce_sum(s);
    if (threadIdx.x == 0) Zinv[blockIdx.x] = 1.0f / s;
}

// ---------------------------------------------------------------------------
// Launch
// ---------------------------------------------------------------------------
extern "C" void kernel_launch(void* const* d_in, const int* in_sizes, int n_in,
                              void* d_out, int out_size) {
    const float* vf    = (const float*)d_in[0];  // vision_feats
    const float* embed = (const float*)d_in[1];  // llm_token_embed (32000,2048)
    const float* W1w   = (const float*)d_in[2];  // (2048,4608)
    const float* W1b   = (const float*)d_in[3];  // (2048,)
    const float* W2w   = (const float*)d_in[4];  // (32000,2048)
    float* out = (float*)d_out;                  // (8,256,2048) f32

    __half *Xh, *W1h, *Fh, *W2h, *Eh, *Ph;
    float *F, *Zinv;
    cudaGetSymbolAddress((void**)&Xh,   g_Xh);
    cudaGetSymbolAddress((void**)&W1h,  g_W1h);
    cudaGetSymbolAddress((void**)&F,    g_F);
    cudaGetSymbolAddress((void**)&Fh,   g_Fh);
    cudaGetSymbolAddress((void**)&W2h,  g_W2h);
    cudaGetSymbolAddress((void**)&Eh,   g_Eh);
    cudaGetSymbolAddress((void**)&Ph,   g_Ph);
    cudaGetSymbolAddress((void**)&Zinv, g_Zinv);

    cudaFuncSetAttribute(gemm_h<0,false>, cudaFuncAttributeMaxDynamicSharedMemorySize, SMEM_DYN);
    cudaFuncSetAttribute(gemm_h<1,false>, cudaFuncAttributeMaxDynamicSharedMemorySize, SMEM_DYN);
    cudaFuncSetAttribute(gemm_h<2,true>,  cudaFuncAttributeMaxDynamicSharedMemorySize, SMEM_DYN);

    const long nW = (long)V_ * DT_ / 4;   // float4 count for W2 / embed

    // 1) pixel shuffle -> half
    {
        long total2 = (long)MROWS * DSHUF / 2;
        shuffle_kernel<<<(int)((total2 + 255) / 256), 256>>>(vf, (__half2*)Xh);
    }
    // W1 convert (small)
    {
        long n4 = (long)DT_ * DSHUF / 4;
        cvt_half<<<(int)((n4 + 255) / 256), 256>>>((const float4*)W1w, (__half2*)W1h, n4);
    }

    // 2) F = X @ W1^T  (2048x2048, K=4608) + concurrent W2 f32->f16 convert
    //    (grid.y 16 compute tiles + 8 converter rows = 128 converter CTAs)
    gemm_h<0,false><<<dim3(MROWS / BM, DT_ / BN + 8), NTH, SMEM_DYN>>>(
        Xh, W1h, F, nullptr, MROWS, DT_, DSHUF,
        (const float4*)W2w, (__half2*)W2h, nW);
    // 3) bias + LN -> half
    ln_kernel<<<MROWS, 256>>>(F, W1b, Fh);
    // 4) Ph = exp(F @ W2^T)  (2048x32000, K=2048) + fused embed convert slices
    gemm_h<1,false><<<dim3(MROWS / BM, V_ / BN), NTH, SMEM_DYN>>>(
        Fh, W2h, Ph, nullptr, MROWS, V_, DT_,
        (const float4*)embed, (__half2*)Eh, nW);
    // 5) Zinv = 1 / rowsum(Ph)
    rowsum_kernel<<<MROWS, 512>>>(Ph, Zinv);
    // 6) out = (Ph @ Eh) * Zinv[row]   (2048x2048, K=32000, NN direct on embed)
    gemm_h<2,true><<<dim3(MROWS / BM, DT_ / BN), NTH, SMEM_DYN>>>(
        Ph, Eh, out, Zinv, MROWS, DT_, V_, nullptr, nullptr, 0);
}

// round 11
// speedup vs baseline: 1.1444x; 1.0378x over previous
#include <cuda_runtime.h>
#include <cuda_fp16.h>
#include <cstdint>
#include <math.h>

// Problem constants
#define B_      8
#define SEQ_    1024
#define DV_     1152
#define DT_     2048
#define V_      32000
#define MROWS   2048
#define DSHUF   4608
#define LN_EPS  1e-5f

// GEMM tiling: 8 warps, 128x128 CTA tile, 64x32 warp tile, 2 CTAs/SM
#define BM      128
#define BN      128
#define BKH     64                 // K elems per stage
#define STAGES  3
#define NTH     256
#define ASTG    (BM * 128)         // 16KB
#define BSTG    (BN * 128)         // 16KB (NT: 128 n-rows x 128B; NN: 64 k-rows x 256B)
#define STGB    (ASTG + BSTG)      // 32768
#define SMEM_DYN (STAGES * STGB)   // 98304

// Scratch (device globals: allocation-guard-safe)
__device__ __half g_Xh [(size_t)MROWS * DSHUF];
__device__ __half g_W1h[(size_t)DT_   * DSHUF];
__device__ float  g_F  [(size_t)MROWS * DT_];
__device__ __half g_Fh [(size_t)MROWS * DT_];
__device__ __half g_W2h[(size_t)V_    * DT_];
__device__ __half g_Eh [(size_t)V_    * DT_];    // embed as half, original [V, DT]
__device__ __half g_Ph [(size_t)MROWS * V_];     // exp(logits), half
__device__ float  g_Zsum[MROWS];                 // row sums of exp (atomic)

// ---------------------------------------------------------------------------
// helpers
// ---------------------------------------------------------------------------
__device__ __forceinline__ uint32_t smem_u32(const void* p) {
    uint32_t a;
    asm("{ .reg .u64 t; cvta.to.shared.u64 t, %1; cvt.u32.u64 %0, t; }" : "=r"(a) : "l"(p));
    return a;
}
#define CP16(d, s) \
    asm volatile("cp.async.cg.shared.global [%0], [%1], 16;" :: "r"(d), "l"(s))
#define CP_COMMIT()  asm volatile("cp.async.commit_group;")
#define CP_WAIT(n)   asm volatile("cp.async.wait_group %0;" :: "n"(n))

__device__ __forceinline__ void ldsm4(uint32_t& r0, uint32_t& r1, uint32_t& r2,
                                      uint32_t& r3, uint32_t a) {
    asm volatile("ldmatrix.sync.aligned.m8n8.x4.shared.b16 {%0,%1,%2,%3}, [%4];"
                 : "=r"(r0), "=r"(r1), "=r"(r2), "=r"(r3) : "r"(a));
}
__device__ __forceinline__ void ldsm4t(uint32_t& r0, uint32_t& r1, uint32_t& r2,
                                       uint32_t& r3, uint32_t a) {
    asm volatile("ldmatrix.sync.aligned.m8n8.x4.trans.shared.b16 {%0,%1,%2,%3}, [%4];"
                 : "=r"(r0), "=r"(r1), "=r"(r2), "=r"(r3) : "r"(a));
}
__device__ __forceinline__ void mma_f16(float* d, const uint32_t* a,
                                        uint32_t b0, uint32_t b1) {
    asm volatile(
        "mma.sync.aligned.m16n8k16.row.col.f32.f16.f16.f32 "
        "{%0,%1,%2,%3}, {%4,%5,%6,%7}, {%8,%9}, {%0,%1,%2,%3};"
        : "+f"(d[0]), "+f"(d[1]), "+f"(d[2]), "+f"(d[3])
        : "r"(a[0]), "r"(a[1]), "r"(a[2]), "r"(a[3]), "r"(b0), "r"(b1));
}

// ---------------------------------------------------------------------------
// fp16 GEMM, f32 accumulate. 256 threads, 128x128 tile, 64x32 warp tiles,
// BK=64, 3-stage cp.async pipeline, 2 CTAs/SM, single barrier per iter.
//   NN=false: C = A[M,K] * B[N,K]^T   (B K-major)
//   NN=true : C = A[M,K] * B[K,N]     (B N-major, ldmatrix.trans fragments)
// MODE: 0 = f32 store; 1 = half(exp(acc)) + atomic row sums into zsum;
//       2 = f32 * (1/zsum[row]).
// Fused f32->f16 converter (cvt_src/cvt_dst/cvt_n4):
//   MODE 0: extra CTAs (blockIdx.y >= N/BN) are pure converters.
//   MODE 1: every CTA converts a grid-stride slice after its epilogue.
// ---------------------------------------------------------------------------
template<int MODE, bool NN>
__global__ __launch_bounds__(NTH, 2)
void gemm_h(const __half* __restrict__ A, const __half* __restrict__ Bw,
            void* __restrict__ Cv, float* __restrict__ zsum,
            int M, int N, int K,
            const float4* __restrict__ cvt_src, __half2* __restrict__ cvt_dst,
            long cvt_n4)
{
    extern __shared__ __align__(128) char sm[];
    const uint32_t sb = smem_u32(sm);
    const int tid  = threadIdx.x;

    if (MODE == 0 && cvt_src && blockIdx.y >= (unsigned)(N / BN)) {
        // pure converter CTA (concurrent with compute CTAs)
        const long nconv = (long)(gridDim.y - N / BN) * gridDim.x;
        long base   = ((long)(blockIdx.y - N / BN) * gridDim.x + blockIdx.x) * NTH + tid;
        long stride = nconv * NTH;
        for (long i = base; i < cvt_n4; i += stride) {
            float4 v = cvt_src[i];
            cvt_dst[2 * i]     = __floats2half2_rn(v.x, v.y);
            cvt_dst[2 * i + 1] = __floats2half2_rn(v.z, v.w);
        }
        return;
    }

    const int warp = tid >> 5;
    const int lane = tid & 31;
    const int gq   = lane >> 2;
    const int tg   = lane & 3;
    const int wm   = (warp & 1) * 64;     // 2 warps in m
    const int wn   = (warp >> 1) * 32;    // 4 warps in n
    const int bm   = blockIdx.x * BM;
    const int bn   = blockIdx.y * BN;
    const int NK   = K / BKH;
    const int rl   = lane & 15;    // ldmatrix row-in-tile
    const int kh   = lane >> 4;    // ldmatrix half-select

    auto load_stage = [&](int f, int slot) {
        const uint32_t sA = sb + (uint32_t)slot * STGB;
        const uint32_t sB = sA + ASTG;
        const __half* Ag = A + (size_t)bm * K + (size_t)f * BKH;
#pragma unroll
        for (int t = 0; t < 4; t++) {            // A: 128 rows x 8 chunks
            int c = tid + t * NTH;
            int row = c >> 3, g = c & 7;
            CP16(sA + row * 128 + ((g ^ (row & 7)) << 4),
                 Ag + (size_t)row * K + g * 8);
        }
        if (!NN) {
            const __half* Bg = Bw + (size_t)bn * K + (size_t)f * BKH;
#pragma unroll
            for (int t = 0; t < 4; t++) {        // B: 128 n-rows x 8 chunks
                int c = tid + t * NTH;
                int row = c >> 3, g = c & 7;
                CP16(sB + row * 128 + ((g ^ (row & 7)) << 4),
                     Bg + (size_t)row * K + g * 8);
            }
        } else {
            const __half* Bg = Bw + (size_t)f * BKH * N + bn;
#pragma unroll
            for (int t = 0; t < 4; t++) {        // B: 64 k-rows x 16 chunks (256B/row)
                int c = tid + t * NTH;
                int krow = c >> 4, ng = c & 15;
                CP16(sB + krow * 256 + ((ng ^ (krow & 7)) << 4),
                     Bg + (size_t)krow * N + ng * 8);
            }
        }
    };

    float acc[4][4][4];
#pragma unroll
    for (int i = 0; i < 4; i++)
#pragma unroll
        for (int j = 0; j < 4; j++)
#pragma unroll
            for (int r = 0; r < 4; r++) acc[i][j][r] = 0.f;

    load_stage(0, 0); CP_COMMIT();
    load_stage(1, 1); CP_COMMIT();

    int slot = 0;
    for (int i = 0; i < NK; i++) {
        CP_WAIT(1);
        __syncthreads();

        const uint32_t sA = sb + (uint32_t)slot * STGB;
        const uint32_t sB = sA + ASTG;

#pragma unroll
        for (int ks = 0; ks < 4; ks++) {
            uint32_t a[4][4];
            {
                const int g = ks * 2 + kh;
#pragma unroll
                for (int mi = 0; mi < 4; mi++) {
                    int row = wm + mi * 16 + rl;
                    ldsm4(a[mi][0], a[mi][1], a[mi][2], a[mi][3],
                          sA + row * 128 + ((g ^ (row & 7)) << 4));
                }
            }
            uint32_t bf[2][4];
            if (!NN) {
                const int g = ks * 2 + kh;
#pragma unroll
                for (int n2 = 0; n2 < 2; n2++) {
                    int row = wn + n2 * 16 + rl;
                    ldsm4(bf[n2][0], bf[n2][1], bf[n2][2], bf[n2][3],
                          sB + row * 128 + ((g ^ (row & 7)) << 4));
                }
#pragma unroll
                for (int mi = 0; mi < 4; mi++)
#pragma unroll
                    for (int ni = 0; ni < 4; ni++)
                        mma_f16(acc[mi][ni], a[mi],
                                bf[ni >> 1][ni & 1], bf[ni >> 1][(ni & 1) + 2]);
            } else {
                // trans load: each ldsm4t covers 16 k-rows x 16 n-cols.
#pragma unroll
                for (int n2 = 0; n2 < 2; n2++) {
                    int krow = ks * 16 + rl;
                    int ng = ((wn + n2 * 16) >> 3) + kh;
                    ldsm4t(bf[n2][0], bf[n2][1], bf[n2][2], bf[n2][3],
                           sB + krow * 256 + ((ng ^ (krow & 7)) << 4));
                }
                // trans reg order: {n-lo/k-lo, n-lo/k-hi, n-hi/k-lo, n-hi/k-hi}
#pragma unroll
                for (int mi = 0; mi < 4; mi++)
#pragma unroll
                    for (int ni = 0; ni < 4; ni++)
                        mma_f16(acc[mi][ni], a[mi],
                                bf[ni >> 1][(ni & 1) * 2], bf[ni >> 1][(ni & 1) * 2 + 1]);
            }
        }
        // NOTE: no second barrier. The loads below write stage (i-1)'s slot;
        // every warp past this iteration's top barrier finished stage i-1,
        // and cp.async writes are per-warp disjoint.
        const int f = i + STAGES - 1;
        if (f < NK) {
            int ws = slot + STAGES - 1; if (ws >= STAGES) ws -= STAGES;
            load_stage(f, ws);
        }
        CP_COMMIT();                 // unconditional: stable group FIFO
        if (++slot == STAGES) slot = 0;
    }

    // ---- epilogue ----
#pragma unroll
    for (int mi = 0; mi < 4; mi++) {
        const int r0 = bm + wm + mi * 16 + gq;
        float zs0 = 0.f, zs1 = 0.f;      // MODE 1 row-sum partials
#pragma unroll
        for (int ni = 0; ni < 4; ni++) {
            const int c0 = bn + wn + ni * 8 + tg * 2;
            const float* ap = acc[mi][ni];
            if (MODE == 0) {
                float* C = (float*)Cv;
                *(float2*)(C + (size_t)r0 * N + c0)       = make_float2(ap[0], ap[1]);
                *(float2*)(C + (size_t)(r0 + 8) * N + c0) = make_float2(ap[2], ap[3]);
            } else if (MODE == 1) {
                float e0 = __expf(ap[0]), e1 = __expf(ap[1]);
                float e2 = __expf(ap[2]), e3 = __expf(ap[3]);
                zs0 += e0 + e1;
                zs1 += e2 + e3;
                __half2* C = (__half2*)Cv;
                C[((size_t)r0 * N + c0) >> 1]       = __floats2half2_rn(e0, e1);
                C[((size_t)(r0 + 8) * N + c0) >> 1] = __floats2half2_rn(e2, e3);
            } else {
                const float s0 = 1.0f / zsum[r0];
                const float s1 = 1.0f / zsum[r0 + 8];
                float* C = (float*)Cv;
                *(float2*)(C + (size_t)r0 * N + c0)       = make_float2(ap[0] * s0, ap[1] * s0);
                *(float2*)(C + (size_t)(r0 + 8) * N + c0) = make_float2(ap[2] * s1, ap[3] * s1);
            }
        }
        if (MODE == 1) {
            // reduce over the 4 tg lanes (same gq), then one atomic per row
            zs0 += __shfl_xor_sync(0xffffffff, zs0, 1);
            zs0 += __shfl_xor_sync(0xffffffff, zs0, 2);
            zs1 += __shfl_xor_sync(0xffffffff, zs1, 1);
            zs1 += __shfl_xor_sync(0xffffffff, zs1, 2);
            if (tg == 0) {
                atomicAdd(&zsum[r0], zs0);
                atomicAdd(&zsum[r0 + 8], zs1);
            }
        }
    }

    // ---- fused converter slice (MODE 1: overlaps with later waves) ----
    if (MODE == 1 && cvt_src) {
        const long ncta = (long)gridDim.x * gridDim.y;
        long base   = ((long)blockIdx.y * gridDim.x + blockIdx.x) * NTH + tid;
        long stride = ncta * NTH;
        for (long i = base; i < cvt_n4; i += stride) {
            float4 v = cvt_src[i];
            cvt_dst[2 * i]     = __floats2half2_rn(v.x, v.y);
            cvt_dst[2 * i + 1] = __floats2half2_rn(v.z, v.w);
        }
    }
}

// ---------------------------------------------------------------------------
// pixel shuffle gather -> half (float2 -> half2)
// ---------------------------------------------------------------------------
__global__ void shuffle_kernel(const float* __restrict__ vf, __half2* __restrict__ X) {
    long i2 = (long)blockIdx.x * blockDim.x + threadIdx.x;
    const long total2 = (long)MROWS * DSHUF / 2;
    if (i2 >= total2) return;
    int e  = (int)(i2 % (DSHUF / 2)) * 2;
    long rl = i2 / (DSHUF / 2);
    int l  = (int)(rl % 256);
    int b  = (int)(rl / 256);
    int d  = e % DV_;
    int h  = 2 * (l >> 4) + (e / (2 * DV_));
    int w  = 2 * (l & 15) + ((e % (2 * DV_)) / DV_);
    float2 v = *(const float2*)(vf + ((long)b * SEQ_ + h * 32 + w) * DV_ + d);
    X[i2] = __floats2half2_rn(v.x, v.y);
}

// ---------------------------------------------------------------------------
// f32 -> half convert copy (W1)
// ---------------------------------------------------------------------------
__global__ void cvt_half(const float4* __restrict__ in, __half2* __restrict__ out, long n4) {
    long i = (long)blockIdx.x * blockDim.x + threadIdx.x;
    if (i >= n4) return;
    float4 v = in[i];
    out[2 * i]     = __floats2half2_rn(v.x, v.y);
    out[2 * i + 1] = __floats2half2_rn(v.z, v.w);
}

// ---------------------------------------------------------------------------
// block reduce
// ---------------------------------------------------------------------------
__device__ __forceinline__ float block_reduce_sum(float v) {
    __shared__ float sh[32];
    int lane = threadIdx.x & 31, wid = threadIdx.x >> 5;
#pragma unroll
    for (int o = 16; o > 0; o >>= 1) v += __shfl_xor_sync(0xffffffff, v, o);
    if (lane == 0) sh[wid] = v;
    __syncthreads();
    int nw = blockDim.x >> 5;
    v = (threadIdx.x < nw) ? sh[threadIdx.x] : 0.f;
    if (wid == 0) {
#pragma unroll
        for (int o = 16; o > 0; o >>= 1) v += __shfl_xor_sync(0xffffffff, v, o);
        if (lane == 0) sh[0] = v;
    }
    __syncthreads();
    float r = sh[0];
    __syncthreads();
    return r;
}

// ---------------------------------------------------------------------------
// bias + LayerNorm: F(f32) -> Fh(half); also zeroes Zsum[row] for GEMM2
// ---------------------------------------------------------------------------
__global__ void ln_kernel(const float* __restrict__ F, const float* __restrict__ bias,
                          __half* __restrict__ Fh, float* __restrict__ zsum) {
    if (threadIdx.x == 0) zsum[blockIdx.x] = 0.f;
    const float* p = F + (size_t)blockIdx.x * DT_;
    __half* o = Fh + (size_t)blockIdx.x * DT_;
    float s = 0.f, ss = 0.f;
    for (int i = threadIdx.x; i < DT_; i += blockDim.x) {
        float v = p[i] + bias[i];
        s += v; ss += v * v;
    }
    s  = block_reduce_sum(s);
    ss = block_reduce_sum(ss);
    float mu  = s * (1.0f / DT_);
    float var = ss * (1.0f / DT_) - mu * mu;
    float rstd = rsqrtf(var + LN_EPS);
    for (int i = threadIdx.x; i < DT_; i += blockDim.x)
        o[i] = __float2half_rn((p[i] + bias[i] - mu) * rstd);
}

// ---------------------------------------------------------------------------
// Launch
// ---------------------------------------------------------------------------
extern "C" void kernel_launch(void* const* d_in, const int* in_sizes, int n_in,
                              void* d_out, int out_size) {
    const float* vf    = (const float*)d_in[0];  // vision_feats
    const float* embed = (const float*)d_in[1];  // llm_token_embed (32000,2048)
    const float* W1w   = (const float*)d_in[2];  // (2048,4608)
    const float* W1b   = (const float*)d_in[3];  // (2048,)
    const float* W2w   = (const float*)d_in[4];  // (32000,2048)
    float* out = (float*)d_out;                  // (8,256,2048) f32

    __half *Xh, *W1h, *Fh, *W2h, *Eh, *Ph;
    float *F, *Zsum;
    cudaGetSymbolAddress((void**)&Xh,   g_Xh);
    cudaGetSymbolAddress((void**)&W1h,  g_W1h);
    cudaGetSymbolAddress((void**)&F,    g_F);
    cudaGetSymbolAddress((void**)&Fh,   g_Fh);
    cudaGetSymbolAddress((void**)&W2h,  g_W2h);
    cudaGetSymbolAddress((void**)&Eh,   g_Eh);
    cudaGetSymbolAddress((void**)&Ph,   g_Ph);
    cudaGetSymbolAddress((void**)&Zsum, g_Zsum);

    cudaFuncSetAttribute(gemm_h<0,false>, cudaFuncAttributeMaxDynamicSharedMemorySize, SMEM_DYN);
    cudaFuncSetAttribute(gemm_h<1,false>, cudaFuncAttributeMaxDynamicSharedMemorySize, SMEM_DYN);
    cudaFuncSetAttribute(gemm_h<2,true>,  cudaFuncAttributeMaxDynamicSharedMemorySize, SMEM_DYN);

    const long nW = (long)V_ * DT_ / 4;   // float4 count for W2 / embed

    // 1) pixel shuffle -> half
    {
        long total2 = (long)MROWS * DSHUF / 2;
        shuffle_kernel<<<(int)((total2 + 255) / 256), 256>>>(vf, (__half2*)Xh);
    }
    // W1 convert (small)
    {
        long n4 = (long)DT_ * DSHUF / 4;
        cvt_half<<<(int)((n4 + 255) / 256), 256>>>((const float4*)W1w, (__half2*)W1h, n4);
    }

    // 2) F = X @ W1^T  (2048x2048, K=4608) + concurrent W2 f32->f16 convert
    gemm_h<0,false><<<dim3(MROWS / BM, DT_ / BN + 8), NTH, SMEM_DYN>>>(
        Xh, W1h, F, nullptr, MROWS, DT_, DSHUF,
        (const float4*)W2w, (__half2*)W2h, nW);
    // 3) bias + LN -> half; zero Zsum
    ln_kernel<<<MROWS, 256>>>(F, W1b, Fh, Zsum);
    // 4) Ph = exp(F @ W2^T), Zsum += row sums (atomic)  + fused embed convert
    gemm_h<1,false><<<dim3(MROWS / BM, V_ / BN), NTH, SMEM_DYN>>>(
        Fh, W2h, Ph, Zsum, MROWS, V_, DT_,
        (const float4*)embed, (__half2*)Eh, nW);
    // 5) out = (Ph @ Eh) * (1/Zsum[row])   (2048x2048, K=32000, NN on embed)
    gemm_h<2,true><<<dim3(MROWS / BM, DT_ / BN), NTH, SMEM_DYN>>>(
        Ph, Eh, out, Zsum, MROWS, DT_, V_, nullptr, nullptr, 0);
}

// round 12
// speedup vs baseline: 1.1484x; 1.0034x over previous
#include <cuda_runtime.h>
#include <cuda_fp16.h>
#include <cstdint>
#include <math.h>

// Problem constants
#define B_      8
#define SEQ_    1024
#define DV_     1152
#define DT_     2048
#define V_      32000
#define MROWS   2048
#define DSHUF   4608
#define LN_EPS  1e-5f

// GEMM tiling: 8 warps, 128x128 CTA tile, 64x32 warp tile, 2 CTAs/SM
#define BM      128
#define BN      128
#define BKH     64                 // K elems per stage
#define STAGES  3
#define NTH     256
#define ASTG    (BM * 128)         // 16KB
#define BSTG    (BN * 128)         // 16KB (NT: 128 n-rows x 128B; NN: 64 k-rows x 256B)
#define STGB    (ASTG + BSTG)      // 32768
#define SMEM_DYN (STAGES * STGB)   // 98304

// Scratch (device globals: allocation-guard-safe)
__device__ __half g_Xh [(size_t)MROWS * DSHUF];
__device__ __half g_W1h[(size_t)DT_   * DSHUF];
__device__ float  g_F  [(size_t)MROWS * DT_];
__device__ __half g_Fh [(size_t)MROWS * DT_];
__device__ __half g_W2h[(size_t)V_    * DT_];
__device__ __half g_Eh [(size_t)V_    * DT_];    // embed as half, original [V, DT]
__device__ __half g_Ph [(size_t)MROWS * V_];     // exp(logits), half
__device__ float  g_Zsum[MROWS];                 // row sums of exp (atomic)

// ---------------------------------------------------------------------------
// helpers
// ---------------------------------------------------------------------------
__device__ __forceinline__ uint32_t smem_u32(const void* p) {
    uint32_t a;
    asm("{ .reg .u64 t; cvta.to.shared.u64 t, %1; cvt.u32.u64 %0, t; }" : "=r"(a) : "l"(p));
    return a;
}
#define CP16(d, s) \
    asm volatile("cp.async.cg.shared.global [%0], [%1], 16;" :: "r"(d), "l"(s))
#define CP_COMMIT()  asm volatile("cp.async.commit_group;")
#define CP_WAIT(n)   asm volatile("cp.async.wait_group %0;" :: "n"(n))

__device__ __forceinline__ void ldsm4(uint32_t& r0, uint32_t& r1, uint32_t& r2,
                                      uint32_t& r3, uint32_t a) {
    asm volatile("ldmatrix.sync.aligned.m8n8.x4.shared.b16 {%0,%1,%2,%3}, [%4];"
                 : "=r"(r0), "=r"(r1), "=r"(r2), "=r"(r3) : "r"(a));
}
__device__ __forceinline__ void ldsm4t(uint32_t& r0, uint32_t& r1, uint32_t& r2,
                                       uint32_t& r3, uint32_t a) {
    asm volatile("ldmatrix.sync.aligned.m8n8.x4.trans.shared.b16 {%0,%1,%2,%3}, [%4];"
                 : "=r"(r0), "=r"(r1), "=r"(r2), "=r"(r3) : "r"(a));
}
__device__ __forceinline__ void mma_f16(float* d, const uint32_t* a,
                                        uint32_t b0, uint32_t b1) {
    asm volatile(
        "mma.sync.aligned.m16n8k16.row.col.f32.f16.f16.f32 "
        "{%0,%1,%2,%3}, {%4,%5,%6,%7}, {%8,%9}, {%0,%1,%2,%3};"
        : "+f"(d[0]), "+f"(d[1]), "+f"(d[2]), "+f"(d[3])
        : "r"(a[0]), "r"(a[1]), "r"(a[2]), "r"(a[3]), "r"(b0), "r"(b1));
}

// ---------------------------------------------------------------------------
// fp16 GEMM, f32 accumulate. 256 threads, 128x128 tile, 64x32 warp tiles,
// BK=64, 3-stage cp.async pipeline, 2 CTAs/SM, single barrier per iter.
//   NN=false: C = A[M,K] * B[N,K]^T   (B K-major)
//   NN=true : C = A[M,K] * B[K,N]     (B N-major, ldmatrix.trans fragments)
// MODE: 0 = f32 store; 1 = half(exp(acc)) + atomic row sums into zsum;
//       2 = f32 * (1/zsum[row]).
// Fused f32->f16 converter (cvt_src/cvt_dst/cvt_n4):
//   MODE 0: extra CTAs (blockIdx.y >= N/BN) are pure converters.
//   MODE 1: every CTA converts a grid-stride slice after its epilogue.
// ---------------------------------------------------------------------------
template<int MODE, bool NN>
__global__ __launch_bounds__(NTH, 2)
void gemm_h(const __half* __restrict__ A, const __half* __restrict__ Bw,
            void* __restrict__ Cv, float* __restrict__ zsum,
            int M, int N, int K,
            const float4* __restrict__ cvt_src, __half2* __restrict__ cvt_dst,
            long cvt_n4)
{
    extern __shared__ __align__(128) char sm[];
    const uint32_t sb = smem_u32(sm);
    const int tid  = threadIdx.x;

    if (MODE == 0 && cvt_src && blockIdx.y >= (unsigned)(N / BN)) {
        // pure converter CTA (concurrent with compute CTAs)
        const long nconv = (long)(gridDim.y - N / BN) * gridDim.x;
        long base   = ((long)(blockIdx.y - N / BN) * gridDim.x + blockIdx.x) * NTH + tid;
        long stride = nconv * NTH;
        for (long i = base; i < cvt_n4; i += stride) {
            float4 v = cvt_src[i];
            cvt_dst[2 * i]     = __floats2half2_rn(v.x, v.y);
            cvt_dst[2 * i + 1] = __floats2half2_rn(v.z, v.w);
        }
        return;
    }

    const int warp = tid >> 5;
    const int lane = tid & 31;
    const int gq   = lane >> 2;
    const int tg   = lane & 3;
    const int wm   = (warp & 1) * 64;     // 2 warps in m
    const int wn   = (warp >> 1) * 32;    // 4 warps in n
    const int bm   = blockIdx.x * BM;
    const int bn   = blockIdx.y * BN;
    const int NK   = K / BKH;
    const int rl   = lane & 15;    // ldmatrix row-in-tile
    const int kh   = lane >> 4;    // ldmatrix half-select

    auto load_stage = [&](int f, int slot) {
        const uint32_t sA = sb + (uint32_t)slot * STGB;
        const uint32_t sB = sA + ASTG;
        const __half* Ag = A + (size_t)bm * K + (size_t)f * BKH;
#pragma unroll
        for (int t = 0; t < 4; t++) {            // A: 128 rows x 8 chunks
            int c = tid + t * NTH;
            int row = c >> 3, g = c & 7;
            CP16(sA + row * 128 + ((g ^ (row & 7)) << 4),
                 Ag + (size_t)row * K + g * 8);
        }
        if (!NN) {
            const __half* Bg = Bw + (size_t)bn * K + (size_t)f * BKH;
#pragma unroll
            for (int t = 0; t < 4; t++) {        // B: 128 n-rows x 8 chunks
                int c = tid + t * NTH;
                int row = c >> 3, g = c & 7;
                CP16(sB + row * 128 + ((g ^ (row & 7)) << 4),
                     Bg + (size_t)row * K + g * 8);
            }
        } else {
            const __half* Bg = Bw + (size_t)f * BKH * N + bn;
#pragma unroll
            for (int t = 0; t < 4; t++) {        // B: 64 k-rows x 16 chunks (256B/row)
                int c = tid + t * NTH;
                int krow = c >> 4, ng = c & 15;
                CP16(sB + krow * 256 + ((ng ^ (krow & 7)) << 4),
                     Bg + (size_t)krow * N + ng * 8);
            }
        }
    };

    float acc[4][4][4];
#pragma unroll
    for (int i = 0; i < 4; i++)
#pragma unroll
        for (int j = 0; j < 4; j++)
#pragma unroll
            for (int r = 0; r < 4; r++) acc[i][j][r] = 0.f;

    load_stage(0, 0); CP_COMMIT();
    load_stage(1, 1); CP_COMMIT();

    int slot = 0;
    for (int i = 0; i < NK; i++) {
        CP_WAIT(1);
        __syncthreads();

        const uint32_t sA = sb + (uint32_t)slot * STGB;
        const uint32_t sB = sA + ASTG;

#pragma unroll
        for (int ks = 0; ks < 4; ks++) {
            uint32_t a[4][4];
            {
                const int g = ks * 2 + kh;
#pragma unroll
                for (int mi = 0; mi < 4; mi++) {
                    int row = wm + mi * 16 + rl;
                    ldsm4(a[mi][0], a[mi][1], a[mi][2], a[mi][3],
                          sA + row * 128 + ((g ^ (row & 7)) << 4));
                }
            }
            uint32_t bf[2][4];
            if (!NN) {
                const int g = ks * 2 + kh;
#pragma unroll
                for (int n2 = 0; n2 < 2; n2++) {
                    int row = wn + n2 * 16 + rl;
                    ldsm4(bf[n2][0], bf[n2][1], bf[n2][2], bf[n2][3],
                          sB + row * 128 + ((g ^ (row & 7)) << 4));
                }
#pragma unroll
                for (int mi = 0; mi < 4; mi++)
#pragma unroll
                    for (int ni = 0; ni < 4; ni++)
                        mma_f16(acc[mi][ni], a[mi],
                                bf[ni >> 1][ni & 1], bf[ni >> 1][(ni & 1) + 2]);
            } else {
                // trans load: each ldsm4t covers 16 k-rows x 16 n-cols.
#pragma unroll
                for (int n2 = 0; n2 < 2; n2++) {
                    int krow = ks * 16 + rl;
                    int ng = ((wn + n2 * 16) >> 3) + kh;
                    ldsm4t(bf[n2][0], bf[n2][1], bf[n2][2], bf[n2][3],
                           sB + krow * 256 + ((ng ^ (krow & 7)) << 4));
                }
                // trans reg order: {n-lo/k-lo, n-lo/k-hi, n-hi/k-lo, n-hi/k-hi}
#pragma unroll
                for (int mi = 0; mi < 4; mi++)
#pragma unroll
                    for (int ni = 0; ni < 4; ni++)
                        mma_f16(acc[mi][ni], a[mi],
                                bf[ni >> 1][(ni & 1) * 2], bf[ni >> 1][(ni & 1) * 2 + 1]);
            }
        }
        // NOTE: no second barrier. The loads below write stage (i-1)'s slot;
        // every warp past this iteration's top barrier finished stage i-1,
        // and cp.async writes are per-warp disjoint.
        const int f = i + STAGES - 1;
        if (f < NK) {
            int ws = slot + STAGES - 1; if (ws >= STAGES) ws -= STAGES;
            load_stage(f, ws);
        }
        CP_COMMIT();                 // unconditional: stable group FIFO
        if (++slot == STAGES) slot = 0;
    }

    // ---- epilogue ----
#pragma unroll
    for (int mi = 0; mi < 4; mi++) {
        const int r0 = bm + wm + mi * 16 + gq;
        float zs0 = 0.f, zs1 = 0.f;      // MODE 1 row-sum partials
#pragma unroll
        for (int ni = 0; ni < 4; ni++) {
            const int c0 = bn + wn + ni * 8 + tg * 2;
            const float* ap = acc[mi][ni];
            if (MODE == 0) {
                float* C = (float*)Cv;
                *(float2*)(C + (size_t)r0 * N + c0)       = make_float2(ap[0], ap[1]);
                *(float2*)(C + (size_t)(r0 + 8) * N + c0) = make_float2(ap[2], ap[3]);
            } else if (MODE == 1) {
                float e0 = __expf(ap[0]), e1 = __expf(ap[1]);
                float e2 = __expf(ap[2]), e3 = __expf(ap[3]);
                zs0 += e0 + e1;
                zs1 += e2 + e3;
                __half2* C = (__half2*)Cv;
                C[((size_t)r0 * N + c0) >> 1]       = __floats2half2_rn(e0, e1);
                C[((size_t)(r0 + 8) * N + c0) >> 1] = __floats2half2_rn(e2, e3);
            } else {
                const float s0 = 1.0f / zsum[r0];
                const float s1 = 1.0f / zsum[r0 + 8];
                float* C = (float*)Cv;
                *(float2*)(C + (size_t)r0 * N + c0)       = make_float2(ap[0] * s0, ap[1] * s0);
                *(float2*)(C + (size_t)(r0 + 8) * N + c0) = make_float2(ap[2] * s1, ap[3] * s1);
            }
        }
        if (MODE == 1) {
            // reduce over the 4 tg lanes (same gq), then one atomic per row
            zs0 += __shfl_xor_sync(0xffffffff, zs0, 1);
            zs0 += __shfl_xor_sync(0xffffffff, zs0, 2);
            zs1 += __shfl_xor_sync(0xffffffff, zs1, 1);
            zs1 += __shfl_xor_sync(0xffffffff, zs1, 2);
            if (tg == 0) {
                atomicAdd(&zsum[r0], zs0);
                atomicAdd(&zsum[r0 + 8], zs1);
            }
        }
    }

    // ---- fused converter slice (MODE 1: overlaps with later waves) ----
    if (MODE == 1 && cvt_src) {
        const long ncta = (long)gridDim.x * gridDim.y;
        long base   = ((long)blockIdx.y * gridDim.x + blockIdx.x) * NTH + tid;
        long stride = ncta * NTH;
        for (long i = base; i < cvt_n4; i += stride) {
            float4 v = cvt_src[i];
            cvt_dst[2 * i]     = __floats2half2_rn(v.x, v.y);
            cvt_dst[2 * i + 1] = __floats2half2_rn(v.z, v.w);
        }
    }
}

// ---------------------------------------------------------------------------
// Merged prep: pixel shuffle (vf -> Xh) AND W1 f32->f16 convert, one launch.
// Blocks [0, NB_SHUF) do the shuffle; blocks [NB_SHUF, NB_TOT) convert W1.
// ---------------------------------------------------------------------------
#define NB_SHUF  1184              // covers 4.718M half2 elems at 4 iters/thread
#define NB_W1    592
#define NB_TOT   (NB_SHUF + NB_W1)

__global__ void prep_kernel(const float* __restrict__ vf, __half2* __restrict__ X,
                            const float4* __restrict__ w1, __half2* __restrict__ w1h) {
    if (blockIdx.x < NB_SHUF) {
        const long total2 = (long)MROWS * DSHUF / 2;
        long stride = (long)NB_SHUF * 256;
        for (long i2 = (long)blockIdx.x * 256 + threadIdx.x; i2 < total2; i2 += stride) {
            int e  = (int)(i2 % (DSHUF / 2)) * 2;
            long rl = i2 / (DSHUF / 2);
            int l  = (int)(rl % 256);
            int b  = (int)(rl / 256);
            int d  = e % DV_;
            int h  = 2 * (l >> 4) + (e / (2 * DV_));
            int w  = 2 * (l & 15) + ((e % (2 * DV_)) / DV_);
            float2 v = *(const float2*)(vf + ((long)b * SEQ_ + h * 32 + w) * DV_ + d);
            X[i2] = __floats2half2_rn(v.x, v.y);
        }
    } else {
        const long n4 = (long)DT_ * DSHUF / 4;
        long stride = (long)NB_W1 * 256;
        for (long i = (long)(blockIdx.x - NB_SHUF) * 256 + threadIdx.x; i < n4; i += stride) {
            float4 v = w1[i];
            w1h[2 * i]     = __floats2half2_rn(v.x, v.y);
            w1h[2 * i + 1] = __floats2half2_rn(v.z, v.w);
        }
    }
}

// ---------------------------------------------------------------------------
// block reduce (512 threads)
// ---------------------------------------------------------------------------
__device__ __forceinline__ float block_reduce_sum(float v) {
    __shared__ float sh[32];
    int lane = threadIdx.x & 31, wid = threadIdx.x >> 5;
#pragma unroll
    for (int o = 16; o > 0; o >>= 1) v += __shfl_xor_sync(0xffffffff, v, o);
    if (lane == 0) sh[wid] = v;
    __syncthreads();
    int nw = blockDim.x >> 5;
    v = (threadIdx.x < nw) ? sh[threadIdx.x] : 0.f;
    if (wid == 0) {
#pragma unroll
        for (int o = 16; o > 0; o >>= 1) v += __shfl_xor_sync(0xffffffff, v, o);
        if (lane == 0) sh[0] = v;
    }
    __syncthreads();
    float r = sh[0];
    __syncthreads();
    return r;
}

// ---------------------------------------------------------------------------
// bias + LayerNorm: F(f32) -> Fh(half), vectorized; zeroes Zsum[row].
// 512 threads, each handles 4 float4 = DT_/512/4... DT_=2048: 1 float4/thread.
// ---------------------------------------------------------------------------
__global__ void ln_kernel(const float4* __restrict__ F, const float4* __restrict__ bias,
                          __half2* __restrict__ Fh, float* __restrict__ zsum) {
    if (threadIdx.x == 0) zsum[blockIdx.x] = 0.f;
    const float4* p = F + (size_t)blockIdx.x * (DT_ / 4);
    __half2* o = Fh + (size_t)blockIdx.x * (DT_ / 2);
    // DT_/4 = 512 float4 per row; 512 threads -> one float4 each
    float4 v = p[threadIdx.x];
    float4 bb = bias[threadIdx.x];
    v.x += bb.x; v.y += bb.y; v.z += bb.z; v.w += bb.w;
    float s  = v.x + v.y + v.z + v.w;
    float ss = v.x * v.x + v.y * v.y + v.z * v.z + v.w * v.w;
    s  = block_reduce_sum(s);
    ss = block_reduce_sum(ss);
    float mu  = s * (1.0f / DT_);
    float var = ss * (1.0f / DT_) - mu * mu;
    float rstd = rsqrtf(var + LN_EPS);
    o[2 * threadIdx.x]     = __floats2half2_rn((v.x - mu) * rstd, (v.y - mu) * rstd);
    o[2 * threadIdx.x + 1] = __floats2half2_rn((v.z - mu) * rstd, (v.w - mu) * rstd);
}

// ---------------------------------------------------------------------------
// Launch
// ---------------------------------------------------------------------------
extern "C" void kernel_launch(void* const* d_in, const int* in_sizes, int n_in,
                              void* d_out, int out_size) {
    const float* vf    = (const float*)d_in[0];  // vision_feats
    const float* embed = (const float*)d_in[1];  // llm_token_embed (32000,2048)
    const float* W1w   = (const float*)d_in[2];  // (2048,4608)
    const float* W1b   = (const float*)d_in[3];  // (2048,)
    const float* W2w   = (const float*)d_in[4];  // (32000,2048)
    float* out = (float*)d_out;                  // (8,256,2048) f32

    __half *Xh, *W1h, *Fh, *W2h, *Eh, *Ph;
    float *F, *Zsum;
    cudaGetSymbolAddress((void**)&Xh,   g_Xh);
    cudaGetSymbolAddress((void**)&W1h,  g_W1h);
    cudaGetSymbolAddress((void**)&F,    g_F);
    cudaGetSymbolAddress((void**)&Fh,   g_Fh);
    cudaGetSymbolAddress((void**)&W2h,  g_W2h);
    cudaGetSymbolAddress((void**)&Eh,   g_Eh);
    cudaGetSymbolAddress((void**)&Ph,   g_Ph);
    cudaGetSymbolAddress((void**)&Zsum, g_Zsum);

    cudaFuncSetAttribute(gemm_h<0,false>, cudaFuncAttributeMaxDynamicSharedMemorySize, SMEM_DYN);
    cudaFuncSetAttribute(gemm_h<1,false>, cudaFuncAttributeMaxDynamicSharedMemorySize, SMEM_DYN);
    cudaFuncSetAttribute(gemm_h<2,true>,  cudaFuncAttributeMaxDynamicSharedMemorySize, SMEM_DYN);

    const long nW = (long)V_ * DT_ / 4;   // float4 count for W2 / embed

    // 1) merged prep: pixel shuffle -> Xh  AND  W1 -> W1h (single launch)
    prep_kernel<<<NB_TOT, 256>>>(vf, (__half2*)Xh, (const float4*)W1w, (__half2*)W1h);

    // 2) F = X @ W1^T  (2048x2048, K=4608) + concurrent W2 f32->f16 convert
    gemm_h<0,false><<<dim3(MROWS / BM, DT_ / BN + 8), NTH, SMEM_DYN>>>(
        Xh, W1h, F, nullptr, MROWS, DT_, DSHUF,
        (const float4*)W2w, (__half2*)W2h, nW);
    // 3) bias + LN -> half; zero Zsum
    ln_kernel<<<MROWS, 512>>>((const float4*)F, (const float4*)W1b, (__half2*)Fh, Zsum);
    // 4) Ph = exp(F @ W2^T), Zsum += row sums (atomic)  + fused embed convert
    gemm_h<1,false><<<dim3(MROWS / BM, V_ / BN), NTH, SMEM_DYN>>>(
        Fh, W2h, Ph, Zsum, MROWS, V_, DT_,
        (const float4*)embed, (__half2*)Eh, nW);
    // 5) out = (Ph @ Eh) * (1/Zsum[row])   (2048x2048, K=32000, NN on embed)
    gemm_h<2,true><<<dim3(MROWS / BM, DT_ / BN), NTH, SMEM_DYN>>>(
        Ph, Eh, out, Zsum, MROWS, DT_, V_, nullptr, nullptr, 0);
}